// round 3
// baseline (speedup 1.0000x reference)
#include <cuda_runtime.h>
#include <cstdint>

// ---------------------------------------------------------------------------
// NNUE: out[b] = tanh( relu( relu( (sum_f emb[idx[f,b]]) @ w1^T + b1 ) @ w2^T + b2 ) @ w3^T + b3 )
//
// Trick: layer 1 is linear in the gathered sum, so precompute g = emb @ w1^T
// ([49152,32], 6MB) each launch, then gather 128B/feature instead of 1KB.
// ---------------------------------------------------------------------------

#define FULLMASK 0xffffffffu

constexpr int INPUT_DIM = 49152;
constexpr int EMB_DIM   = 256;
constexpr int BATCH     = 16384;
constexpr int N_FEAT    = 32;

// Scratch: precomputed first-layer table (6.29 MB). Static __device__ global
// (no allocations allowed in kernel_launch).
__device__ float g_tbl[INPUT_DIM * 32];

// Packed dual-FMA on the fp32 pipe (sm_100+): d = a*b + d on two lanes.
__device__ __forceinline__ void fma2(unsigned long long& d,
                                     unsigned long long a,
                                     unsigned long long b) {
    asm("fma.rn.f32x2 %0, %1, %2, %0;" : "+l"(d) : "l"(a), "l"(b));
}

// ---------------------------------------------------------------------------
// Kernel 1: g_tbl[i][j] = dot(emb[i, :], w1[j, :])   i<49152, j<32, k<256
//
// 256 threads = 8 warps, each warp computes K1_R=8 rows. lane = j.
// - w1 in smem, row stride 260 floats -> conflict-free LDS.128
//   (stride/4 = 65 === 1 mod 8: the 8-lane phases hit distinct 16B banks).
// - Per 32-wide k-chunk: lane register-caches its w1[j] chunk (8x ulonglong2),
//   emb rows staged coalesced into smem (row stride 36 floats, 16B-aligned)
//   and consumed via broadcast LDS.128 (broadcast == conflict-free).
// - fma.rn.f32x2 halves fp32-pipe instruction count.
// Static smem: 32*260*4 + 8*8*36*4 = 33280 + 9216 = 42496 B < 48K limit.
// ---------------------------------------------------------------------------
constexpr int K1_WARPS = 8;
constexpr int K1_R     = 8;                        // rows per warp
constexpr int K1_ROWS_PER_BLOCK = K1_WARPS * K1_R; // 64

__global__ __launch_bounds__(256, 2)
void k1_precompute(const float* __restrict__ emb, const float* __restrict__ w1) {
    __shared__ __align__(16) float w1s[32 * 260];
    __shared__ __align__(16) float es[K1_WARPS][K1_R * 36];

    const int tid = threadIdx.x;

    // Cooperative load of w1 into padded smem.
    for (int t = tid; t < 32 * 256; t += 256)
        w1s[(t >> 8) * 260 + (t & 255)] = w1[t];
    __syncthreads();

    const int warp = tid >> 5;
    const int lane = tid & 31;
    const int rowBase = blockIdx.x * K1_ROWS_PER_BLOCK + warp * K1_R;
    float* esw = es[warp];

    unsigned long long acc[K1_R];
#pragma unroll
    for (int r = 0; r < K1_R; r++) acc[r] = 0ull;

#pragma unroll 1
    for (int c = 0; c < 8; ++c) {                 // 8 chunks of 32 k-values
        // Register-cache this lane's w1 chunk: w1[lane][c*32 .. c*32+31]
        ulonglong2 wreg[8];
#pragma unroll
        for (int t = 0; t < 8; t++)
            wreg[t] = *(const ulonglong2*)&w1s[lane * 260 + c * 32 + t * 4];

        // Stage emb rows [rowBase..rowBase+7], k in [c*32, c*32+32), coalesced.
        // lanes 0-7 cover one 128B row-chunk; 4 rows per pass, 2 passes.
#pragma unroll
        for (int t = 0; t < 2; t++) {
            const int r = t * 4 + (lane >> 3);
            const float4 v = *(const float4*)&emb[(size_t)(rowBase + r) * EMB_DIM
                                                  + c * 32 + (lane & 7) * 4];
            *(float4*)&esw[r * 36 + (lane & 7) * 4] = v;
        }
        __syncwarp();

#pragma unroll
        for (int r = 0; r < K1_R; r++) {
            unsigned long long a = acc[r];
#pragma unroll
            for (int t = 0; t < 8; t++) {
                const ulonglong2 e = *(const ulonglong2*)&esw[r * 36 + t * 4];
                fma2(a, e.x, wreg[t].x);
                fma2(a, e.y, wreg[t].y);
            }
            acc[r] = a;
        }
        __syncwarp();   // before next chunk overwrites esw
    }

#pragma unroll
    for (int r = 0; r < K1_R; r++) {
        const float lo = __uint_as_float((unsigned)(acc[r] & 0xffffffffull));
        const float hi = __uint_as_float((unsigned)(acc[r] >> 32));
        g_tbl[(size_t)(rowBase + r) * 32 + lane] = lo + hi;
    }
}

// ---------------------------------------------------------------------------
// Kernel 2: per batch element b (one warp each, lane = neuron j):
//   acc[j] = b1[j] + sum_f g_tbl[idx[f,b]][j]           (32 coalesced 128B loads)
//   h1 = relu(acc); h2[j] = relu(b2[j] + sum_k shfl(h1,k) * w2[j][k])
//   out[b] = tanh(b3 + sum_j h2[j]*w3[j])               (warp reduction)
// w2 in smem with row stride 33 -> bank (j+k)%32, conflict-free.
// ---------------------------------------------------------------------------
__global__ __launch_bounds__(256)
void k2_forward(const int* __restrict__ indices,
                const float* __restrict__ b1,
                const float* __restrict__ w2,
                const float* __restrict__ b2,
                const float* __restrict__ w3,
                const float* __restrict__ b3,
                float* __restrict__ out) {
    __shared__ float w2s[32 * 33];
    __shared__ float w3s[32];

    const int tid = threadIdx.x;
    for (int t = tid; t < 1024; t += 256)
        w2s[(t >> 5) * 33 + (t & 31)] = w2[t];
    if (tid < 32) w3s[tid] = w3[tid];
    __syncthreads();

    const int lane = tid & 31;
    const int b = blockIdx.x * 8 + (tid >> 5);

    // lane f loads the index for feature f of this batch element.
    const int my_idx = indices[lane * BATCH + b];

    float acc = b1[lane];
#pragma unroll
    for (int f = 0; f < N_FEAT; ++f) {
        const int id = __shfl_sync(FULLMASK, my_idx, f);
        acc += g_tbl[(size_t)id * 32 + lane];
    }
    const float h1 = fmaxf(acc, 0.0f);

    float h2 = b2[lane];
#pragma unroll
    for (int k = 0; k < 32; ++k) {
        const float a = __shfl_sync(FULLMASK, h1, k);
        h2 = fmaf(a, w2s[lane * 33 + k], h2);
    }
    h2 = fmaxf(h2, 0.0f);

    float p = h2 * w3s[lane];
#pragma unroll
    for (int off = 16; off; off >>= 1)
        p += __shfl_xor_sync(FULLMASK, p, off);

    if (lane == 0)
        out[b] = tanhf(p + b3[0]);
}

// ---------------------------------------------------------------------------
extern "C" void kernel_launch(void* const* d_in, const int* in_sizes, int n_in,
                              void* d_out, int out_size) {
    const int*   indices = (const int*)  d_in[0];
    const float* emb     = (const float*)d_in[1];
    const float* w1      = (const float*)d_in[2];
    const float* b1      = (const float*)d_in[3];
    const float* w2      = (const float*)d_in[4];
    const float* b2      = (const float*)d_in[5];
    const float* w3      = (const float*)d_in[6];
    const float* b3      = (const float*)d_in[7];
    float* out = (float*)d_out;

    k1_precompute<<<INPUT_DIM / K1_ROWS_PER_BLOCK, 256>>>(emb, w1);   // 768 blocks
    k2_forward<<<BATCH / 8, 256>>>(indices, b1, w2, b2, w3, b3, out); // 2048 blocks
}

// round 5
// speedup vs baseline: 1.1054x; 1.1054x over previous
#include <cuda_runtime.h>
#include <cstdint>

// ---------------------------------------------------------------------------
// NNUE: out[b] = tanh(relu(relu((sum_f emb[idx[f,b]]) @ w1^T + b1) @ w2^T + b2) @ w3^T + b3)
//
// K1: g_tbl = emb @ w1^T ([49152,32]) — SIMT FFMA2, designed FMA-pipe-bound:
//     w1 chunk register-cached and amortized over 16 rows/warp, emb staged
//     coalesced via smem with register prefetch of the next chunk.
// K2: 32-feature gather (128B rows) + tiny MLP, one warp per batch element,
//     block-staged indices (coalesced load -> broadcast LDS).
// ---------------------------------------------------------------------------

#define FULLMASK 0xffffffffu
typedef unsigned long long ull;

constexpr int INPUT_DIM = 49152;
constexpr int EMB_DIM   = 256;
constexpr int BATCH     = 16384;
constexpr int N_FEAT    = 32;

__device__ float g_tbl[INPUT_DIM * 32];

// Packed dual-FMA on the fp32 pipe (sm_100): d = a*b + d on two f32 lanes.
__device__ __forceinline__ void fma2(ull& d, ull a, ull b) {
    asm("fma.rn.f32x2 %0, %1, %2, %0;" : "+l"(d) : "l"(a), "l"(b));
}

// ---------------------------------------------------------------------------
// Kernel 1: g_tbl[i][j] = dot(emb[i,:], w1[j,:])   i<49152, j<32, k<256
//
// 256 threads = 8 warps, each warp computes 16 rows; lane = output col j.
// Per 32-wide k-chunk:
//   - lane register-caches w1[j][chunk] (8x LDS.128, conflict-free: row
//     stride 260 floats -> per-phase banks 4j..4j+3)
//   - emb rows staged coalesced (LDG.128 prefetched one chunk ahead into
//     registers, STS.128 to padded smem stride 36), consumed via broadcast
//     LDS.128 (1 wavefront each)
//   - 16 rows x 16 FFMA2 = 256 FFMA2 (512 FMA-pipe cyc) dominates ~170 LSU
//     wavefronts -> FMA-bound.
// Dynamic smem: 32*260*4 + 8*16*36*4 = 33280 + 18432 = 51712 B (x2 CTA/SM).
// ---------------------------------------------------------------------------
constexpr int K1_WARPS = 8;
constexpr int K1_R     = 16;                       // rows per warp
constexpr int K1_ROWS_PER_BLOCK = K1_WARPS * K1_R; // 128
constexpr int K1_SMEM  = (32 * 260 + K1_WARPS * K1_R * 36) * 4; // 51712 B

__global__ __launch_bounds__(256, 2)
void k1_precompute(const float* __restrict__ emb, const float* __restrict__ w1) {
    extern __shared__ __align__(16) float dsm[];
    float* w1s = dsm;                                   // 32 x 260
    const int tid  = threadIdx.x;
    const int warp = tid >> 5;
    const int lane = tid & 31;
    float* esw = dsm + 32 * 260 + warp * (K1_R * 36);   // 16 x 36 per warp

    // Cooperative load of w1 into padded smem.
    for (int t = tid; t < 32 * 256; t += 256)
        w1s[(t >> 8) * 260 + (t & 255)] = w1[t];
    __syncthreads();

    const int rowBase = blockIdx.x * K1_ROWS_PER_BLOCK + warp * K1_R;
    const int myRow = lane >> 3;        // 0..3, this lane's staging row offset
    const int mySeg = (lane & 7) * 4;   // 16B segment within the 128B row chunk

    ull acc[K1_R];
#pragma unroll
    for (int r = 0; r < K1_R; r++) acc[r] = 0ull;

    // Prefetch chunk 0 emb data into registers (4 rows per lane-group pass).
    float4 pre[4];
#pragma unroll
    for (int t = 0; t < 4; t++)
        pre[t] = *(const float4*)&emb[(size_t)(rowBase + t * 4 + myRow) * EMB_DIM + mySeg];

#pragma unroll 1
    for (int c = 0; c < 8; ++c) {                 // 8 chunks of 32 k-values
        // Commit prefetched emb chunk to smem.
#pragma unroll
        for (int t = 0; t < 4; t++)
            *(float4*)&esw[(t * 4 + myRow) * 36 + mySeg] = pre[t];

        // Register-cache this lane's w1 chunk: w1[lane][c*32 .. c*32+31].
        ulonglong2 wreg[8];
#pragma unroll
        for (int t = 0; t < 8; t++)
            wreg[t] = *(const ulonglong2*)&w1s[lane * 260 + c * 32 + t * 4];

        __syncwarp();

        // Prefetch next chunk while FMAs run.
        if (c < 7) {
#pragma unroll
            for (int t = 0; t < 4; t++)
                pre[t] = *(const float4*)&emb[(size_t)(rowBase + t * 4 + myRow) * EMB_DIM
                                              + (c + 1) * 32 + mySeg];
        }

#pragma unroll
        for (int r = 0; r < K1_R; r++) {
            ull a = acc[r];
#pragma unroll
            for (int t = 0; t < 8; t++) {
                const ulonglong2 e = *(const ulonglong2*)&esw[r * 36 + t * 4];
                fma2(a, e.x, wreg[t].x);
                fma2(a, e.y, wreg[t].y);
            }
            acc[r] = a;
        }
        __syncwarp();   // before next chunk overwrites esw
    }

#pragma unroll
    for (int r = 0; r < K1_R; r++) {
        const float lo = __uint_as_float((unsigned)(acc[r] & 0xffffffffull));
        const float hi = __uint_as_float((unsigned)(acc[r] >> 32));
        g_tbl[(size_t)(rowBase + r) * 32 + lane] = lo + hi;
    }
}

// ---------------------------------------------------------------------------
// Kernel 2: per batch element b (one warp each, lane = neuron j):
//   acc[j] = b1[j] + sum_f g_tbl[idx[f,b]][j]     (32 coalesced 128B loads)
//   h1 = relu(acc); h2[j] = relu(b2[j] + sum_k shfl(h1,k)*w2[j][k])
//   out[b] = tanh(b3 + sum_j h2[j]*w3[j])
// Indices are block-staged: coalesced LDG into smem, broadcast LDS reads
// (replaces the 32-line spread idx load + 32-shfl chain of R3).
// ---------------------------------------------------------------------------
__global__ __launch_bounds__(256)
void k2_forward(const int* __restrict__ indices,
                const float* __restrict__ b1,
                const float* __restrict__ w2,
                const float* __restrict__ b2,
                const float* __restrict__ w3,
                const float* __restrict__ b3,
                float* __restrict__ out) {
    __shared__ float w2s[32 * 33];
    __shared__ float w3s[32];
    __shared__ int   idx_s[32][8];

    const int tid = threadIdx.x;
    const int b0 = blockIdx.x * 8;

    for (int t = tid; t < 1024; t += 256)
        w2s[(t >> 5) * 33 + (t & 31)] = w2[t];
    if (tid < 32) w3s[tid] = w3[tid];
    // Stage this block's 32 features x 8 elems of indices, coalesced (32B runs).
    {
        const int f = tid >> 3, e = tid & 7;
        idx_s[f][e] = indices[f * BATCH + b0 + e];
    }
    __syncthreads();

    const int lane = tid & 31;
    const int e = tid >> 5;
    const int b = b0 + e;

    float acc0 = b1[lane], acc1 = 0.0f;
#pragma unroll
    for (int f = 0; f < N_FEAT; f += 2) {
        const int i0 = idx_s[f][e];       // broadcast LDS
        const int i1 = idx_s[f + 1][e];
        acc0 += g_tbl[(size_t)i0 * 32 + lane];
        acc1 += g_tbl[(size_t)i1 * 32 + lane];
    }
    const float h1 = fmaxf(acc0 + acc1, 0.0f);

    float h2 = b2[lane];
#pragma unroll
    for (int k = 0; k < 32; ++k) {
        const float a = __shfl_sync(FULLMASK, h1, k);
        h2 = fmaf(a, w2s[lane * 33 + k], h2);
    }
    h2 = fmaxf(h2, 0.0f);

    float p = h2 * w3s[lane];
#pragma unroll
    for (int off = 16; off; off >>= 1)
        p += __shfl_xor_sync(FULLMASK, p, off);

    if (lane == 0)
        out[b] = tanhf(p + b3[0]);
}

// ---------------------------------------------------------------------------
extern "C" void kernel_launch(void* const* d_in, const int* in_sizes, int n_in,
                              void* d_out, int out_size) {
    const int*   indices = (const int*)  d_in[0];
    const float* emb     = (const float*)d_in[1];
    const float* w1      = (const float*)d_in[2];
    const float* b1      = (const float*)d_in[3];
    const float* w2      = (const float*)d_in[4];
    const float* b2      = (const float*)d_in[5];
    const float* w3      = (const float*)d_in[6];
    const float* b3      = (const float*)d_in[7];
    float* out = (float*)d_out;

    static bool attr_set = false;
    if (!attr_set) {
        cudaFuncSetAttribute(k1_precompute,
                             cudaFuncAttributeMaxDynamicSharedMemorySize, K1_SMEM);
        attr_set = true;
    }

    k1_precompute<<<INPUT_DIM / K1_ROWS_PER_BLOCK, 256, K1_SMEM>>>(emb, w1); // 384 blocks
    k2_forward<<<BATCH / 8, 256>>>(indices, b1, w2, b2, w3, b3, out);        // 2048 blocks
}

// round 6
// speedup vs baseline: 1.3348x; 1.2076x over previous
#include <cuda_runtime.h>
#include <cstdint>

// ---------------------------------------------------------------------------
// NNUE: out[b] = tanh(relu(relu((sum_f emb[idx[f,b]]) @ w1^T + b1) @ w2^T + b2) @ w3^T + b3)
//
// K1: g_tbl = emb @ w1^T ([49152,32]) — SIMT FFMA2 with 2D register tiling:
//     warp tile 32x32, thread tile 4 rows x 8 cols. Per k-step: 16 FFMA2 vs
//     12 LSU wavefronts (4 broadcast LDS.32 for e, 4 LDS.64 for packed w
//     pairs) -> FMA-pipe bound by design.
// K2: 32-feature gather (128B rows) + tiny MLP, one warp per batch element.
//     MIO diet: int4 idx loads, w2 row register-resident, 4-way gather ILP.
// ---------------------------------------------------------------------------

#define FULLMASK 0xffffffffu
typedef unsigned long long ull;

constexpr int INPUT_DIM = 49152;
constexpr int EMB_DIM   = 256;
constexpr int BATCH     = 16384;

__device__ float g_tbl[INPUT_DIM * 32];

// Packed dual-FMA on the fp32 pipe: d = a*b + d on two f32 lanes.
__device__ __forceinline__ void fma2(ull& d, ull a, ull b) {
    asm("fma.rn.f32x2 %0, %1, %2, %0;" : "+l"(d) : "l"(a), "l"(b));
}
// Duplicate one float into both halves of an f32x2 operand (1 ALU op).
__device__ __forceinline__ ull dup2(float x) {
    ull d;
    asm("mov.b64 %0, {%1, %1};" : "=l"(d) : "f"(x));
    return d;
}

// ---------------------------------------------------------------------------
// Kernel 1: g_tbl[i][j] = dot(emb[i,:], w1[j,:])   i<49152, j<32, k<256
//
// CTA: 128 threads = 4 warps, each warp owns 32 rows; grid 384.
// Lane decomposition: tr = lane>>2 (8 row groups of 4), tj = lane&3 (4 col
// groups of 8). Thread accumulates 4 rows x 8 cols as 16 f32x2 (j-paired).
// smem:
//   w_t[k][j], stride 34 (even -> LDS.64 8B-aligned; banks tj*8 apart)
//   e_t[k][r] per warp, stride 33 (LDS.32 broadcast, banks tr*4 apart; STS
//   fill pattern hits all 32 banks exactly once)
// Per k: e 4x LDS.32 (1 wf ea) + w 4x LDS.64 (2 wf ea) + 4 dup + 16 FFMA2
//   -> 12 wf : 32 FMA cyc : 28 issue slots  => FMA-bound.
// ---------------------------------------------------------------------------
constexpr int K1_THREADS = 128;
constexpr int K1_ROWS_PER_BLOCK = 128;     // 4 warps x 32 rows
constexpr int WT_STRIDE = 34;              // w_t row stride (floats)
constexpr int ET_STRIDE = 33;              // e_t row stride (floats)
constexpr int K1_SMEM = (256 * WT_STRIDE + 4 * 32 * ET_STRIDE) * 4; // 51712 B

__global__ __launch_bounds__(K1_THREADS, 4)
void k1_precompute(const float* __restrict__ emb, const float* __restrict__ w1) {
    extern __shared__ __align__(16) float dsm[];
    float* w_t   = dsm;                          // [256][34]
    float* e_all = dsm + 256 * WT_STRIDE;

    const int tid  = threadIdx.x;
    const int warp = tid >> 5;
    const int lane = tid & 31;

    // Fill w_t transposed: w_t[k][j] = w1[j][k]. Coalesced read, bank-clean STS.
    for (int t = tid; t < 32 * 256; t += K1_THREADS) {
        const int j = t >> 8, k = t & 255;
        w_t[k * WT_STRIDE + j] = w1[t];
    }
    __syncthreads();

    float* e_t = e_all + warp * (32 * ET_STRIDE);   // [32 k][32 r]
    const int tr = lane >> 2;       // 0..7  -> rows tr*4 .. tr*4+3
    const int tj = lane & 3;        // 0..3  -> cols tj*8 .. tj*8+7
    const int rowBase = blockIdx.x * K1_ROWS_PER_BLOCK + warp * 32;

    // Staging pattern: pass t covers row t*4 + (lane>>3), 16B seg (lane&7)*4.
    const int sRow = lane >> 3;          // 0..3
    const int sSeg = (lane & 7) * 4;     // 0,4,..28 (k offset within chunk)

    ull acc[4][4];
#pragma unroll
    for (int r = 0; r < 4; r++)
#pragma unroll
        for (int p = 0; p < 4; p++) acc[r][p] = 0ull;

    // Prefetch chunk 0.
    float4 pre[8];
#pragma unroll
    for (int t = 0; t < 8; t++)
        pre[t] = *(const float4*)&emb[(size_t)(rowBase + t * 4 + sRow) * EMB_DIM + sSeg];

#pragma unroll 1
    for (int c = 0; c < 8; ++c) {
        // Commit prefetched emb chunk, transposed: e_t[k][r].
        // Banks: (sSeg+i)*33 + row  ===  (lane&7)*4 + i + t*4 + (lane>>3) mod 32
        //        -> all 32 lanes distinct. 1 wf per STS.
#pragma unroll
        for (int t = 0; t < 8; t++) {
            const int row = t * 4 + sRow;
            e_t[(sSeg + 0) * ET_STRIDE + row] = pre[t].x;
            e_t[(sSeg + 1) * ET_STRIDE + row] = pre[t].y;
            e_t[(sSeg + 2) * ET_STRIDE + row] = pre[t].z;
            e_t[(sSeg + 3) * ET_STRIDE + row] = pre[t].w;
        }
        __syncwarp();

        // Prefetch next chunk while FMAs run.
        if (c < 7) {
#pragma unroll
            for (int t = 0; t < 8; t++)
                pre[t] = *(const float4*)&emb[(size_t)(rowBase + t * 4 + sRow) * EMB_DIM
                                              + (c + 1) * 32 + sSeg];
        }

        const float* wrow = &w_t[(c * 32) * WT_STRIDE + tj * 8];
        const float* erow = &e_t[tr * 4];
#pragma unroll
        for (int k = 0; k < 32; ++k) {
            // w pairs: direct LDS.64 of (j, j+1) — already the f32x2 operand.
            const ull w0 = *(const ull*)(wrow + 0);
            const ull w1v = *(const ull*)(wrow + 2);
            const ull w2v = *(const ull*)(wrow + 4);
            const ull w3v = *(const ull*)(wrow + 6);
            // e broadcast loads + duplicate into both halves.
            const ull e0 = dup2(erow[0]);
            const ull e1 = dup2(erow[1]);
            const ull e2 = dup2(erow[2]);
            const ull e3 = dup2(erow[3]);
            fma2(acc[0][0], e0, w0); fma2(acc[0][1], e0, w1v);
            fma2(acc[0][2], e0, w2v); fma2(acc[0][3], e0, w3v);
            fma2(acc[1][0], e1, w0); fma2(acc[1][1], e1, w1v);
            fma2(acc[1][2], e1, w2v); fma2(acc[1][3], e1, w3v);
            fma2(acc[2][0], e2, w0); fma2(acc[2][1], e2, w1v);
            fma2(acc[2][2], e2, w2v); fma2(acc[2][3], e2, w3v);
            fma2(acc[3][0], e3, w0); fma2(acc[3][1], e3, w1v);
            fma2(acc[3][2], e3, w2v); fma2(acc[3][3], e3, w3v);
            wrow += WT_STRIDE;
            erow += ET_STRIDE;
        }
        __syncwarp();   // before next chunk overwrites e_t
    }

    // Epilogue: thread owns rows (tr*4 + r), cols tj*8..tj*8+7 (contiguous).
#pragma unroll
    for (int r = 0; r < 4; r++) {
        const int row = rowBase + tr * 4 + r;
        float* dst = &g_tbl[(size_t)row * 32 + tj * 8];
        float2 a0 = *(float2*)&acc[r][0];
        float2 a1 = *(float2*)&acc[r][1];
        float2 a2 = *(float2*)&acc[r][2];
        float2 a3 = *(float2*)&acc[r][3];
        *(float4*)(dst)     = make_float4(a0.x, a0.y, a1.x, a1.y);
        *(float4*)(dst + 4) = make_float4(a2.x, a2.y, a3.x, a3.y);
    }
}

// ---------------------------------------------------------------------------
// Kernel 2: per batch element b (one warp each, lane = neuron j):
//   acc[j] = b1[j] + sum_f g_tbl[idx[f,b]][j]    (32 coalesced 128B gathers)
//   h1 = relu(acc); h2[j] = relu(b2[j] + sum_k shfl(h1,k)*w2reg[k])
//   out[b] = tanh(b3 + sum_j h2[j]*w3[j])
// MIO diet vs R5: idx as 8 uniform LDS.128 (int4), w2 row register-resident
// (8 LDS.128 once instead of 32 LDS.32 in-loop), 4 gather accumulators.
// ---------------------------------------------------------------------------
__global__ __launch_bounds__(256)
void k2_forward(const int* __restrict__ indices,
                const float* __restrict__ b1,
                const float* __restrict__ w2,
                const float* __restrict__ b2,
                const float* __restrict__ w3,
                const float* __restrict__ b3,
                float* __restrict__ out) {
    __shared__ __align__(16) float w2s[32 * 36];
    __shared__ float w3s[32];
    __shared__ __align__(16) int idx_s[8][32];

    const int tid = threadIdx.x;
    const int b0 = blockIdx.x * 8;

    // w2 staged with stride 36 (16B-aligned rows for LDS.128 readback).
    for (int t = tid; t < 1024; t += 256)
        w2s[(t >> 5) * 36 + (t & 31)] = w2[t];
    if (tid < 32) w3s[tid] = w3[tid];
    // Stage indices: 32B-coalesced runs, laid out [elem][feature].
    {
        const int f = tid >> 3, e = tid & 7;
        idx_s[e][f] = indices[f * BATCH + b0 + e];
    }
    __syncthreads();

    const int lane = tid & 31;
    const int e = tid >> 5;
    const int b = b0 + e;

    // Register-resident w2 row for this lane (8 conflict-free LDS.128).
    float4 wrow[8];
#pragma unroll
    for (int i = 0; i < 8; i++)
        wrow[i] = *(const float4*)&w2s[lane * 36 + i * 4];

    const int4* ip = (const int4*)idx_s[e];
    float acc0 = b1[lane], acc1 = 0.f, acc2 = 0.f, acc3 = 0.f;
#pragma unroll
    for (int q = 0; q < 8; ++q) {
        const int4 i4 = ip[q];                     // uniform LDS.128
        acc0 += g_tbl[(size_t)i4.x * 32 + lane];
        acc1 += g_tbl[(size_t)i4.y * 32 + lane];
        acc2 += g_tbl[(size_t)i4.z * 32 + lane];
        acc3 += g_tbl[(size_t)i4.w * 32 + lane];
    }
    const float h1 = fmaxf((acc0 + acc1) + (acc2 + acc3), 0.0f);

    float h2 = b2[lane];
    const float* wr = (const float*)wrow;
#pragma unroll
    for (int k = 0; k < 32; ++k) {
        const float a = __shfl_sync(FULLMASK, h1, k);
        h2 = fmaf(a, wr[k], h2);
    }
    h2 = fmaxf(h2, 0.0f);

    float p = h2 * w3s[lane];
#pragma unroll
    for (int off = 16; off; off >>= 1)
        p += __shfl_xor_sync(FULLMASK, p, off);

    if (lane == 0)
        out[b] = tanhf(p + b3[0]);
}

// ---------------------------------------------------------------------------
extern "C" void kernel_launch(void* const* d_in, const int* in_sizes, int n_in,
                              void* d_out, int out_size) {
    const int*   indices = (const int*)  d_in[0];
    const float* emb     = (const float*)d_in[1];
    const float* w1      = (const float*)d_in[2];
    const float* b1      = (const float*)d_in[3];
    const float* w2      = (const float*)d_in[4];
    const float* b2      = (const float*)d_in[5];
    const float* w3      = (const float*)d_in[6];
    const float* b3      = (const float*)d_in[7];
    float* out = (float*)d_out;

    static bool attr_set = false;
    if (!attr_set) {
        cudaFuncSetAttribute(k1_precompute,
                             cudaFuncAttributeMaxDynamicSharedMemorySize, K1_SMEM);
        attr_set = true;
    }

    k1_precompute<<<INPUT_DIM / K1_ROWS_PER_BLOCK, K1_THREADS, K1_SMEM>>>(emb, w1); // 384 blocks
    k2_forward<<<BATCH / 8, 256>>>(indices, b1, w2, b2, w3, b3, out);               // 2048 blocks
}

// round 7
// speedup vs baseline: 1.4456x; 1.0830x over previous
#include <cuda_runtime.h>
#include <cstdint>

// ---------------------------------------------------------------------------
// NNUE: out[b] = tanh(relu(relu((sum_f emb[idx[f,b]]) @ w1^T + b1) @ w2^T + b2) @ w3^T + b3)
//
// K1: g_tbl = emb @ w1^T ([49152,32]).
//     Row-paired f32x2 accumulators: warp tile 64 rows x 32 cols, thread tile
//     4 rowpairs x 8 cols. Per k-step/warp: 4 LDS.64 (e rowpairs, broadcast)
//     + 4 LDS.64 (w col-pairs, unpack free + dup) = 8 wf vs 32 FFMA2 -> FMA-
//     pipe bound (LSU 87%). CTA = 4 warps, K split 2-way across warp pairs
//     (SMSP balance: 384 CTAs of 4 warps) with smem partial reduction.
// K2: 32-feature gather (128B rows) + tiny MLP; 2 elems per warp interleaved.
// ---------------------------------------------------------------------------

#define FULLMASK 0xffffffffu
typedef unsigned long long ull;

constexpr int INPUT_DIM = 49152;
constexpr int EMB_DIM   = 256;
constexpr int BATCH     = 16384;

__device__ float g_tbl[INPUT_DIM * 32];

__device__ __forceinline__ void fma2(ull& d, ull a, ull b) {
    asm("fma.rn.f32x2 %0, %1, %2, %0;" : "+l"(d) : "l"(a), "l"(b));
}
__device__ __forceinline__ void add2(ull& d, ull a) {
    asm("add.rn.f32x2 %0, %0, %1;" : "+l"(d) : "l"(a));
}
__device__ __forceinline__ ull dup2(float x) {
    ull d; asm("mov.b64 %0, {%1, %1};" : "=l"(d) : "f"(x)); return d;
}
__device__ __forceinline__ void unpack2(ull v, float& a, float& b) {
    asm("mov.b64 {%0, %1}, %2;" : "=f"(a), "=f"(b) : "l"(v));
}

// ---------------------------------------------------------------------------
// Kernel 1.  CTA: 128 threads = 4 warps; 128 rows per CTA; grid 384.
//   warp w: rows (w&1)*64..+63, k-half (w>>1)*128..+127.
// smem (dynamic, 68608 B -> 3 CTAs/SM):
//   w_t[256][34]  f32 transposed weights (34816 B)
//   e[4 warps][16 k][33 ull] rowpair-packed emb staging (4224 B/warp)
//   red[2][32 slot][33 ull]  k-split partials (8448 B/half)
// Mainloop chunk = 16 k. Per k: e LDS.64 x4 (rp = tr+8q -> distinct banks),
//   w LDS.64 x4 (+free unpack, 8 dup movs), 32 FFMA2.
// ---------------------------------------------------------------------------
constexpr int K1_THREADS = 128;
constexpr int K1_SMEM    = 34816 + 4 * 4224 + 2 * 8448;   // 68608

__global__ __launch_bounds__(K1_THREADS, 3)
void k1_precompute(const float* __restrict__ emb, const float* __restrict__ w1) {
    extern __shared__ __align__(16) float dsm[];
    float* w_t  = dsm;                                  // [256][34]
    ull*  e_all = (ull*)(dsm + 8704);                   // 4 x [16][33]
    ull*  red   = (ull*)(dsm + 8704 + 4224);            // 2 x [32][33]

    const int tid  = threadIdx.x;
    const int wid  = tid >> 5;
    const int lane = tid & 31;

    // Fill w_t transposed: w_t[k][j] = w1[j*256+k]. Coalesced LDG, 2-wf STS.
    for (int t = tid; t < 8192; t += K1_THREADS)
        w_t[(t & 255) * 34 + (t >> 8)] = w1[t];
    __syncthreads();

    const int rowHalf = wid & 1;
    const int kHalf   = wid >> 1;
    const int rowBase = blockIdx.x * 128 + rowHalf * 64;
    const int kBase   = kHalf * 128;

    ull*   e_u = e_all + wid * (16 * 33);
    float* e_f = (float*)e_u;

    const int tr   = lane >> 2;        // 0..7
    const int tj   = lane & 3;         // 0..3 -> cols tj*8..+7
    const int sSeg = (lane & 3) * 4;   // staging k-offset 0,4,8,12

    ull acc[4][8];
#pragma unroll
    for (int q = 0; q < 4; q++)
#pragma unroll
        for (int p = 0; p < 8; p++) acc[q][p] = 0ull;

    // Prefetch chunk 0: pass t covers row t*8+tr, 16 floats via 4 lanes.
    const float* gbase = emb + (size_t)rowBase * EMB_DIM + kBase + sSeg;
    float4 pre[8];
#pragma unroll
    for (int t = 0; t < 8; t++)
        pre[t] = *(const float4*)(gbase + (size_t)(t * 8 + tr) * EMB_DIM);

#pragma unroll 1
    for (int c = 0; c < 8; ++c) {
        // Commit staged chunk: float slot = k_local*66 + row_local
        // (row_local = rp*2+odd). Banks: 2*sSeg {0,8,16,24} + rl {0..7}: all 32.
#pragma unroll
        for (int t = 0; t < 8; t++) {
            const int rl = t * 8 + tr;
            e_f[(sSeg + 0) * 66 + rl] = pre[t].x;
            e_f[(sSeg + 1) * 66 + rl] = pre[t].y;
            e_f[(sSeg + 2) * 66 + rl] = pre[t].z;
            e_f[(sSeg + 3) * 66 + rl] = pre[t].w;
        }
        __syncwarp();

        if (c < 7) {
            const float* gb = gbase + (c + 1) * 16;
#pragma unroll
            for (int t = 0; t < 8; t++)
                pre[t] = *(const float4*)(gb + (size_t)(t * 8 + tr) * EMB_DIM);
        }

        const float* wp = w_t + (size_t)(kBase + c * 16) * 34 + tj * 8;
        const ull*   ep = e_u;
#pragma unroll
        for (int k = 0; k < 16; ++k) {
            // w col-pairs; unpack is register-half aliasing (free) + dup movs.
            ull wd[8];
#pragma unroll
            for (int m = 0; m < 4; m++) {
                const ull wpair = *(const ull*)(wp + 2 * m);
                float wa, wb; unpack2(wpair, wa, wb);
                wd[2 * m]     = dup2(wa);
                wd[2 * m + 1] = dup2(wb);
            }
            // e rowpairs rp = tr + 8q: banks 2tr+16q distinct per instr.
            const ull e0 = ep[tr];
            const ull e1 = ep[tr + 8];
            const ull e2 = ep[tr + 16];
            const ull e3 = ep[tr + 24];
#pragma unroll
            for (int p = 0; p < 8; p++) {
                fma2(acc[0][p], e0, wd[p]);
                fma2(acc[1][p], e1, wd[p]);
                fma2(acc[2][p], e2, wd[p]);
                fma2(acc[3][p], e3, wd[p]);
            }
            wp += 34;
            ep += 33;
        }
        __syncwarp();
    }

    // ---- K-split reduction: warps 2,3 publish partials; warps 0,1 combine ----
    __syncthreads();
    ull* redh = red + rowHalf * (32 * 33);
    if (kHalf) {
#pragma unroll
        for (int q = 0; q < 4; q++)
#pragma unroll
            for (int p = 0; p < 8; p++)
                redh[(q * 8 + p) * 33 + lane] = acc[q][p];
    }
    __syncthreads();
    if (!kHalf) {
#pragma unroll
        for (int q = 0; q < 4; q++)
#pragma unroll
            for (int p = 0; p < 8; p++)
                add2(acc[q][p], redh[(q * 8 + p) * 33 + lane]);

        // Store: rows 2*(tr+8q)+h, cols tj*8..+7 (two STG.128 per row).
#pragma unroll
        for (int q = 0; q < 4; q++) {
#pragma unroll
            for (int h = 0; h < 2; h++) {
                const int row = rowBase + (tr + 8 * q) * 2 + h;
                float v[8];
#pragma unroll
                for (int p = 0; p < 8; p++) {
                    float a, b; unpack2(acc[q][p], a, b);
                    v[p] = h ? b : a;
                }
                float* dst = &g_tbl[(size_t)row * 32 + tj * 8];
                *(float4*)(dst)     = make_float4(v[0], v[1], v[2], v[3]);
                *(float4*)(dst + 4) = make_float4(v[4], v[5], v[6], v[7]);
            }
        }
    }
}

// ---------------------------------------------------------------------------
// Kernel 2: 16 batch elems per block (grid 1024); each warp handles 2 elems
// with interleaved gather / layer-2 shfl chains / reductions (latency overlap,
// w2-row preload amortized 2x). lane = neuron j.
// ---------------------------------------------------------------------------
__global__ __launch_bounds__(256)
void k2_forward(const int* __restrict__ indices,
                const float* __restrict__ b1,
                const float* __restrict__ w2,
                const float* __restrict__ b2,
                const float* __restrict__ w3,
                const float* __restrict__ b3,
                float* __restrict__ out) {
    __shared__ __align__(16) float w2s[32 * 36];
    __shared__ float w3s[32];
    __shared__ __align__(16) int idx_s[16][36];   // stride 36: 16B-aligned rows

    const int tid = threadIdx.x;
    const int b0 = blockIdx.x * 16;

    for (int t = tid; t < 1024; t += 256)
        w2s[(t >> 5) * 36 + (t & 31)] = w2[t];
    if (tid < 32) w3s[tid] = w3[tid];
    // Stage indices [elem][feature]; coalesced 64B runs.
    for (int t = tid; t < 512; t += 256) {
        const int f = t >> 4, e = t & 15;
        idx_s[e][f] = indices[f * BATCH + b0 + e];
    }
    __syncthreads();

    const int lane = tid & 31;
    const int e0 = (tid >> 5) * 2;

    // Register-resident w2 row for this lane.
    float4 wrow[8];
#pragma unroll
    for (int i = 0; i < 8; i++)
        wrow[i] = *(const float4*)&w2s[lane * 36 + i * 4];

    const int4* ipa = (const int4*)idx_s[e0];
    const int4* ipb = (const int4*)idx_s[e0 + 1];

    float a0 = b1[lane], a1 = 0.f;
    float c0 = a0,       c1 = 0.f;
#pragma unroll
    for (int q = 0; q < 8; ++q) {
        const int4 ia = ipa[q];                    // uniform LDS.128
        const int4 ib = ipb[q];
        a0 += g_tbl[(size_t)ia.x * 32 + lane];
        c0 += g_tbl[(size_t)ib.x * 32 + lane];
        a1 += g_tbl[(size_t)ia.y * 32 + lane];
        c1 += g_tbl[(size_t)ib.y * 32 + lane];
        a0 += g_tbl[(size_t)ia.z * 32 + lane];
        c0 += g_tbl[(size_t)ib.z * 32 + lane];
        a1 += g_tbl[(size_t)ia.w * 32 + lane];
        c1 += g_tbl[(size_t)ib.w * 32 + lane];
    }
    const float h1a = fmaxf(a0 + a1, 0.0f);
    const float h1b = fmaxf(c0 + c1, 0.0f);

    float h2a = b2[lane], h2b = h2a;
    const float* wr = (const float*)wrow;
#pragma unroll
    for (int k = 0; k < 32; ++k) {
        const float va = __shfl_sync(FULLMASK, h1a, k);
        const float vb = __shfl_sync(FULLMASK, h1b, k);
        h2a = fmaf(va, wr[k], h2a);
        h2b = fmaf(vb, wr[k], h2b);
    }
    h2a = fmaxf(h2a, 0.0f);
    h2b = fmaxf(h2b, 0.0f);

    float pa = h2a * w3s[lane];
    float pb = h2b * w3s[lane];
#pragma unroll
    for (int off = 16; off; off >>= 1) {
        pa += __shfl_xor_sync(FULLMASK, pa, off);
        pb += __shfl_xor_sync(FULLMASK, pb, off);
    }

    const float r = (lane & 1) ? pb : pa;
    if (lane < 2)
        out[b0 + e0 + lane] = tanhf(r + b3[0]);
}

// ---------------------------------------------------------------------------
extern "C" void kernel_launch(void* const* d_in, const int* in_sizes, int n_in,
                              void* d_out, int out_size) {
    const int*   indices = (const int*)  d_in[0];
    const float* emb     = (const float*)d_in[1];
    const float* w1      = (const float*)d_in[2];
    const float* b1      = (const float*)d_in[3];
    const float* w2      = (const float*)d_in[4];
    const float* b2      = (const float*)d_in[5];
    const float* w3      = (const float*)d_in[6];
    const float* b3      = (const float*)d_in[7];
    float* out = (float*)d_out;

    static bool attr_set = false;
    if (!attr_set) {
        cudaFuncSetAttribute(k1_precompute,
                             cudaFuncAttributeMaxDynamicSharedMemorySize, K1_SMEM);
        attr_set = true;
    }

    k1_precompute<<<INPUT_DIM / 128, K1_THREADS, K1_SMEM>>>(emb, w1);  // 384 blocks
    k2_forward<<<BATCH / 16, 256>>>(indices, b1, w2, b2, w3, b3, out); // 1024 blocks
}

// round 9
// speedup vs baseline: 1.7502x; 1.2107x over previous
#include <cuda_runtime.h>
#include <cuda_bf16.h>
#include <cstdint>

// ---------------------------------------------------------------------------
// NNUE: out[b] = tanh(relu(relu((sum_f emb[idx[f,b]]) @ w1^T + b1) @ w2^T + b2) @ w3^T + b3)
//
// K1: g_tbl = emb @ w1^T ([49152,32]) via legacy tensor-core PTX
//     mma.sync.m16n8k16 bf16 with hi/lo split: emb = Ah + Al, w1 = Bh + Bl,
//     D = Ah*Bh + Al*Bh + Ah*Bl (f32 accum). Dropped Al*Bl <= 2^-16 rel.
// K2: 32-feature gather (128B rows) + tiny MLP, 2 elems/warp (R7, unchanged).
// ---------------------------------------------------------------------------

#define FULLMASK 0xffffffffu

constexpr int INPUT_DIM = 49152;
constexpr int EMB_DIM   = 256;
constexpr int BATCH     = 16384;

__device__ float g_tbl[INPUT_DIM * 32];

__device__ __forceinline__ uint32_t smem_u32(const void* p) {
    uint32_t a;
    asm("{ .reg .u64 t; cvta.to.shared.u64 t, %1; cvt.u32.u64 %0, t; }" : "=r"(a) : "l"(p));
    return a;
}
__device__ __forceinline__ void ldmat_x4(uint32_t r[4], uint32_t addr) {
    asm volatile("ldmatrix.sync.aligned.m8n8.x4.shared.b16 {%0,%1,%2,%3}, [%4];"
                 : "=r"(r[0]), "=r"(r[1]), "=r"(r[2]), "=r"(r[3]) : "r"(addr));
}
__device__ __forceinline__ void mma_bf16(float d[4], const uint32_t a[4],
                                         uint32_t b0, uint32_t b1) {
    asm volatile("mma.sync.aligned.m16n8k16.row.col.f32.bf16.bf16.f32 "
                 "{%0,%1,%2,%3}, {%4,%5,%6,%7}, {%8,%9}, {%0,%1,%2,%3};"
                 : "+f"(d[0]), "+f"(d[1]), "+f"(d[2]), "+f"(d[3])
                 : "r"(a[0]), "r"(a[1]), "r"(a[2]), "r"(a[3]), "r"(b0), "r"(b1));
}

// Split float2 -> (hi bf16x2 packed, lo bf16x2 packed).
__device__ __forceinline__ void split2(float x, float y, uint32_t& hi, uint32_t& lo) {
    __nv_bfloat162 h = __float22bfloat162_rn(make_float2(x, y));
    float2 hf = __bfloat1622float2(h);
    __nv_bfloat162 l = __float22bfloat162_rn(make_float2(x - hf.x, y - hf.y));
    hi = *(uint32_t*)&h;
    lo = *(uint32_t*)&l;
}

// ---------------------------------------------------------------------------
// Kernel 1.  CTA: 128 threads = 4 warps; 128 rows per CTA; grid 384.
// Warp w: rows w*32..+31, full N=32, K looped in 16 chunks of 16.
// Dynamic smem (54272 B):
//   AH/AL: [128 rows][16 k] bf16, row stride 80 B  (10240 B each)
//   BH/BL: [32 n][256 k] bf16, row stride 528 B = 512 data + 16 pad
//          (16896 B each; pad keeps ldmatrix row segments off one bank column)
// Per chunk per warp: 4 A-ldmatrix.x4 + 4 B-ldmatrix.x4 + 24 HMMA.
// ---------------------------------------------------------------------------
constexpr int A_STRIDE = 80;    // bytes per A row (16 bf16 + 48 pad)
constexpr int B_STRIDE = 528;   // bytes per B row (256 bf16 = 512 + 16 pad)
constexpr int SZ_A = 128 * A_STRIDE;          // 10240
constexpr int SZ_B = 32 * B_STRIDE;           // 16896
constexpr int K1_SMEM = 2 * SZ_A + 2 * SZ_B;  // 54272

__global__ __launch_bounds__(128)
void k1_precompute(const float* __restrict__ emb, const float* __restrict__ w1) {
    extern __shared__ __align__(16) char dsm[];
    char* sAH = dsm;
    char* sAL = dsm + SZ_A;
    char* sBH = dsm + 2 * SZ_A;
    char* sBL = dsm + 2 * SZ_A + SZ_B;

    const int tid  = threadIdx.x;
    const int wid  = tid >> 5;
    const int lane = tid & 31;
    const int rowBase = blockIdx.x * 128;

    // ---- Prologue: convert w1 (32x256) into BH/BL ----
    {
        const float4* src = (const float4*)w1;
        for (int i = tid; i < 2048; i += 128) {
            const float4 v = src[i];
            const int n = i >> 6;                 // 64 float4 per row
            const int k = (i & 63) * 4;
            uint32_t h0, l0, h1, l1;
            split2(v.x, v.y, h0, l0);
            split2(v.z, v.w, h1, l1);
            const int off = n * B_STRIDE + k * 2;
            *(uint2*)(sBH + off) = make_uint2(h0, h1);
            *(uint2*)(sBL + off) = make_uint2(l0, l1);
        }
    }

    // ---- Load + convert A chunk 0 ----
    const int aRow = tid >> 2;            // 0..31 within pass group
    const int aSeg = tid & 3;             // float4 seg within 16-k chunk
    {
#pragma unroll
        for (int p = 0; p < 4; p++) {
            const int row = p * 32 + aRow;
            const float4 v = *(const float4*)&emb[(size_t)(rowBase + row) * EMB_DIM + aSeg * 4];
            uint32_t h0, l0, h1, l1;
            split2(v.x, v.y, h0, l0);
            split2(v.z, v.w, h1, l1);
            const int off = row * A_STRIDE + aSeg * 8;
            *(uint2*)(sAH + off) = make_uint2(h0, h1);
            *(uint2*)(sAL + off) = make_uint2(l0, l1);
        }
    }
    __syncthreads();

    // ldmatrix base addresses for this lane.
    const uint32_t aBaseH = smem_u32(sAH) + (uint32_t)((wid * 32 + (lane & 15)) * A_STRIDE + (lane >> 4) * 16);
    const uint32_t aBaseL = smem_u32(sAL) + (uint32_t)((wid * 32 + (lane & 15)) * A_STRIDE + (lane >> 4) * 16);
    // B: lanes 0-7: n0-7/k0-7, 8-15: n0-7/k8-15, 16-23: n8-15/k0-7, 24-31: n8-15/k8-15.
    const int bN0 = (lane & 7) + ((lane >> 4) & 1) * 8;
    const uint32_t bKoff = (uint32_t)(((lane >> 3) & 1) * 16);   // bytes
    const uint32_t bBaseH0 = smem_u32(sBH) + (uint32_t)(bN0 * B_STRIDE) + bKoff;
    const uint32_t bBaseH1 = bBaseH0 + 16 * B_STRIDE;
    const uint32_t bBaseL0 = smem_u32(sBL) + (uint32_t)(bN0 * B_STRIDE) + bKoff;
    const uint32_t bBaseL1 = bBaseL0 + 16 * B_STRIDE;

    float d[2][4][4];
#pragma unroll
    for (int mt = 0; mt < 2; mt++)
#pragma unroll
        for (int nt = 0; nt < 4; nt++)
#pragma unroll
            for (int r = 0; r < 4; r++) d[mt][nt][r] = 0.0f;

#pragma unroll 1
    for (int c = 0; c < 16; ++c) {
        // Load fragments for this chunk (k = c*16 .. +15).
        uint32_t aH[2][4], aL[2][4];
        ldmat_x4(aH[0], aBaseH);
        ldmat_x4(aH[1], aBaseH + 16 * A_STRIDE);
        ldmat_x4(aL[0], aBaseL);
        ldmat_x4(aL[1], aBaseL + 16 * A_STRIDE);

        const uint32_t bk = (uint32_t)(c * 32);    // c*16 bf16 = c*32 bytes
        uint32_t bH01[4], bH23[4], bL01[4], bL23[4];
        ldmat_x4(bH01, bBaseH0 + bk);
        ldmat_x4(bH23, bBaseH1 + bk);
        ldmat_x4(bL01, bBaseL0 + bk);
        ldmat_x4(bL23, bBaseL1 + bk);

        // Prefetch next A chunk while tensor ops run.
        float4 pre[4];
        if (c < 15) {
#pragma unroll
            for (int p = 0; p < 4; p++)
                pre[p] = *(const float4*)&emb[(size_t)(rowBase + p * 32 + aRow) * EMB_DIM
                                              + (c + 1) * 16 + aSeg * 4];
        }

        // 24 HMMA: (Ah,Bh), (Al,Bh), (Ah,Bl) for 2 m-tiles x 4 n-tiles.
#pragma unroll
        for (int mt = 0; mt < 2; mt++) {
            mma_bf16(d[mt][0], aH[mt], bH01[0], bH01[1]);
            mma_bf16(d[mt][1], aH[mt], bH01[2], bH01[3]);
            mma_bf16(d[mt][2], aH[mt], bH23[0], bH23[1]);
            mma_bf16(d[mt][3], aH[mt], bH23[2], bH23[3]);
            mma_bf16(d[mt][0], aL[mt], bH01[0], bH01[1]);
            mma_bf16(d[mt][1], aL[mt], bH01[2], bH01[3]);
            mma_bf16(d[mt][2], aL[mt], bH23[0], bH23[1]);
            mma_bf16(d[mt][3], aL[mt], bH23[2], bH23[3]);
            mma_bf16(d[mt][0], aH[mt], bL01[0], bL01[1]);
            mma_bf16(d[mt][1], aH[mt], bL01[2], bL01[3]);
            mma_bf16(d[mt][2], aH[mt], bL23[0], bL23[1]);
            mma_bf16(d[mt][3], aH[mt], bL23[2], bL23[3]);
        }

        __syncthreads();      // everyone done reading A chunk c
        if (c < 15) {
#pragma unroll
            for (int p = 0; p < 4; p++) {
                const int row = p * 32 + aRow;
                uint32_t h0, l0, h1, l1;
                split2(pre[p].x, pre[p].y, h0, l0);
                split2(pre[p].z, pre[p].w, h1, l1);
                const int off = row * A_STRIDE + aSeg * 8;
                *(uint2*)(sAH + off) = make_uint2(h0, h1);
                *(uint2*)(sAL + off) = make_uint2(l0, l1);
            }
            __syncthreads();
        }
    }

    // ---- Epilogue: D fragment -> g_tbl. lane: rows l/4 (+8), cols 2(l%4). ----
    const int g = lane >> 2;
    const int cp = (lane & 3) * 2;
#pragma unroll
    for (int mt = 0; mt < 2; mt++) {
        const int r0 = rowBase + wid * 32 + mt * 16 + g;
#pragma unroll
        for (int nt = 0; nt < 4; nt++) {
            const int col = nt * 8 + cp;
            *(float2*)&g_tbl[(size_t)r0 * 32 + col]       = make_float2(d[mt][nt][0], d[mt][nt][1]);
            *(float2*)&g_tbl[(size_t)(r0 + 8) * 32 + col] = make_float2(d[mt][nt][2], d[mt][nt][3]);
        }
    }
}

// ---------------------------------------------------------------------------
// Kernel 2 (R7, unchanged): 16 elems/block, 2 elems per warp interleaved.
// ---------------------------------------------------------------------------
__global__ __launch_bounds__(256)
void k2_forward(const int* __restrict__ indices,
                const float* __restrict__ b1,
                const float* __restrict__ w2,
                const float* __restrict__ b2,
                const float* __restrict__ w3,
                const float* __restrict__ b3,
                float* __restrict__ out) {
    __shared__ __align__(16) float w2s[32 * 36];
    __shared__ float w3s[32];
    __shared__ __align__(16) int idx_s[16][36];

    const int tid = threadIdx.x;
    const int b0 = blockIdx.x * 16;

    for (int t = tid; t < 1024; t += 256)
        w2s[(t >> 5) * 36 + (t & 31)] = w2[t];
    if (tid < 32) w3s[tid] = w3[tid];
    for (int t = tid; t < 512; t += 256) {
        const int f = t >> 4, e = t & 15;
        idx_s[e][f] = indices[f * BATCH + b0 + e];
    }
    __syncthreads();

    const int lane = tid & 31;
    const int e0 = (tid >> 5) * 2;

    float4 wrow[8];
#pragma unroll
    for (int i = 0; i < 8; i++)
        wrow[i] = *(const float4*)&w2s[lane * 36 + i * 4];

    const int4* ipa = (const int4*)idx_s[e0];
    const int4* ipb = (const int4*)idx_s[e0 + 1];

    float a0 = b1[lane], a1 = 0.f;
    float c0 = a0,       c1 = 0.f;
#pragma unroll
    for (int q = 0; q < 8; ++q) {
        const int4 ia = ipa[q];
        const int4 ib = ipb[q];
        a0 += g_tbl[(size_t)ia.x * 32 + lane];
        c0 += g_tbl[(size_t)ib.x * 32 + lane];
        a1 += g_tbl[(size_t)ia.y * 32 + lane];
        c1 += g_tbl[(size_t)ib.y * 32 + lane];
        a0 += g_tbl[(size_t)ia.z * 32 + lane];
        c0 += g_tbl[(size_t)ib.z * 32 + lane];
        a1 += g_tbl[(size_t)ia.w * 32 + lane];
        c1 += g_tbl[(size_t)ib.w * 32 + lane];
    }
    const float h1a = fmaxf(a0 + a1, 0.0f);
    const float h1b = fmaxf(c0 + c1, 0.0f);

    float h2a = b2[lane], h2b = h2a;
    const float* wr = (const float*)wrow;
#pragma unroll
    for (int k = 0; k < 32; ++k) {
        const float va = __shfl_sync(FULLMASK, h1a, k);
        const float vb = __shfl_sync(FULLMASK, h1b, k);
        h2a = fmaf(va, wr[k], h2a);
        h2b = fmaf(vb, wr[k], h2b);
    }
    h2a = fmaxf(h2a, 0.0f);
    h2b = fmaxf(h2b, 0.0f);

    float pa = h2a * w3s[lane];
    float pb = h2b * w3s[lane];
#pragma unroll
    for (int off = 16; off; off >>= 1) {
        pa += __shfl_xor_sync(FULLMASK, pa, off);
        pb += __shfl_xor_sync(FULLMASK, pb, off);
    }

    const float r = (lane & 1) ? pb : pa;
    if (lane < 2)
        out[b0 + e0 + lane] = tanhf(r + b3[0]);
}

// ---------------------------------------------------------------------------
extern "C" void kernel_launch(void* const* d_in, const int* in_sizes, int n_in,
                              void* d_out, int out_size) {
    const int*   indices = (const int*)  d_in[0];
    const float* emb     = (const float*)d_in[1];
    const float* w1      = (const float*)d_in[2];
    const float* b1      = (const float*)d_in[3];
    const float* w2      = (const float*)d_in[4];
    const float* b2      = (const float*)d_in[5];
    const float* w3      = (const float*)d_in[6];
    const float* b3      = (const float*)d_in[7];
    float* out = (float*)d_out;

    static bool attr_set = false;
    if (!attr_set) {
        cudaFuncSetAttribute(k1_precompute,
                             cudaFuncAttributeMaxDynamicSharedMemorySize, K1_SMEM);
        attr_set = true;
    }

    k1_precompute<<<INPUT_DIM / 128, 128, K1_SMEM>>>(emb, w1);         // 384 blocks
    k2_forward<<<BATCH / 16, 256>>>(indices, b1, w2, b2, w3, b3, out); // 1024 blocks
}

// round 10
// speedup vs baseline: 1.8649x; 1.0655x over previous
#include <cuda_runtime.h>
#include <cuda_bf16.h>
#include <cstdint>

// ---------------------------------------------------------------------------
// NNUE: out[b] = tanh(relu(relu((sum_f emb[idx[f,b]]) @ w1^T + b1) @ w2^T + b2) @ w3^T + b3)
//
// K1: g_tbl = emb @ w1^T ([49152,32]) via mma.sync.m16n8k16 bf16 hi/lo split
//     (Ah*Bh + Al*Bh + Ah*Bl, f32 accum). Double-buffered A staging, 32-k
//     chunks, one __syncthreads per chunk.
// K2: thread-per-(elem, float4-segment) gather: 16 independent LDG.128 per
//     thread (latency -> BW bound), smem partials, then warp MLP (R7 phase).
// ---------------------------------------------------------------------------

#define FULLMASK 0xffffffffu

constexpr int INPUT_DIM = 49152;
constexpr int EMB_DIM   = 256;
constexpr int BATCH     = 16384;

__device__ float g_tbl[INPUT_DIM * 32];

__device__ __forceinline__ uint32_t smem_u32(const void* p) {
    uint32_t a;
    asm("{ .reg .u64 t; cvta.to.shared.u64 t, %1; cvt.u32.u64 %0, t; }" : "=r"(a) : "l"(p));
    return a;
}
__device__ __forceinline__ void ldmat_x4(uint32_t r[4], uint32_t addr) {
    asm volatile("ldmatrix.sync.aligned.m8n8.x4.shared.b16 {%0,%1,%2,%3}, [%4];"
                 : "=r"(r[0]), "=r"(r[1]), "=r"(r[2]), "=r"(r[3]) : "r"(addr));
}
__device__ __forceinline__ void mma_bf16(float d[4], const uint32_t a[4],
                                         uint32_t b0, uint32_t b1) {
    asm volatile("mma.sync.aligned.m16n8k16.row.col.f32.bf16.bf16.f32 "
                 "{%0,%1,%2,%3}, {%4,%5,%6,%7}, {%8,%9}, {%0,%1,%2,%3};"
                 : "+f"(d[0]), "+f"(d[1]), "+f"(d[2]), "+f"(d[3])
                 : "r"(a[0]), "r"(a[1]), "r"(a[2]), "r"(a[3]), "r"(b0), "r"(b1));
}
__device__ __forceinline__ void split2(float x, float y, uint32_t& hi, uint32_t& lo) {
    __nv_bfloat162 h = __float22bfloat162_rn(make_float2(x, y));
    float2 hf = __bfloat1622float2(h);
    __nv_bfloat162 l = __float22bfloat162_rn(make_float2(x - hf.x, y - hf.y));
    hi = *(uint32_t*)&h;
    lo = *(uint32_t*)&l;
}

// ---------------------------------------------------------------------------
// Kernel 1.  CTA: 128 threads = 4 warps; 128 rows; grid 384.
// K processed in 8 chunks of 32; A double-buffered (hi/lo), B resident.
// Dynamic smem: 4 A-bufs (2 stages x hi/lo) x 10240 + BH/BL x 16896 = 74752 B.
// Per chunk per warp: 16 ldmatrix.x4 + 48 HMMA + 1 sync.
// ---------------------------------------------------------------------------
constexpr int A_STRIDE = 80;    // bytes per A row: 32 bf16 = 64 + 16 pad
constexpr int B_STRIDE = 528;   // bytes per B row: 256 bf16 = 512 + 16 pad
constexpr int SZ_A = 128 * A_STRIDE;                  // 10240
constexpr int SZ_B = 32 * B_STRIDE;                   // 16896
constexpr int K1_SMEM = 4 * SZ_A + 2 * SZ_B;          // 74752

__global__ __launch_bounds__(128)
void k1_precompute(const float* __restrict__ emb, const float* __restrict__ w1) {
    extern __shared__ __align__(16) char dsm[];
    char* sA[2][2];                        // [stage][hi=0/lo=1]
    sA[0][0] = dsm;
    sA[0][1] = dsm + SZ_A;
    sA[1][0] = dsm + 2 * SZ_A;
    sA[1][1] = dsm + 3 * SZ_A;
    char* sBH = dsm + 4 * SZ_A;
    char* sBL = sBH + SZ_B;

    const int tid  = threadIdx.x;
    const int wid  = tid >> 5;
    const int lane = tid & 31;
    const int rowBase = blockIdx.x * 128;

    // ---- Prologue: convert w1 (32x256) into BH/BL ----
    {
        const float4* src = (const float4*)w1;
        for (int i = tid; i < 2048; i += 128) {
            const float4 v = src[i];
            const int n = i >> 6;
            const int k = (i & 63) * 4;
            uint32_t h0, l0, h1, l1;
            split2(v.x, v.y, h0, l0);
            split2(v.z, v.w, h1, l1);
            const int off = n * B_STRIDE + k * 2;
            *(uint2*)(sBH + off) = make_uint2(h0, h1);
            *(uint2*)(sBL + off) = make_uint2(l0, l1);
        }
    }

    // A staging pattern: thread covers rows p*16 + gRow (p=0..7), float4 seg
    // gSeg of the 32-k window (row = 128 B, 8 lanes -> perfectly coalesced).
    const int gRow = tid >> 3;          // 0..15
    const int gSeg = tid & 7;           // 0..7

    // ---- Stage chunk 0 into buffer 0 ----
    {
#pragma unroll
        for (int p = 0; p < 8; p++) {
            const int row = p * 16 + gRow;
            const float4 v = *(const float4*)&emb[(size_t)(rowBase + row) * EMB_DIM + gSeg * 4];
            uint32_t h0, l0, h1, l1;
            split2(v.x, v.y, h0, l0);
            split2(v.z, v.w, h1, l1);
            const int off = row * A_STRIDE + gSeg * 8;
            *(uint2*)(sA[0][0] + off) = make_uint2(h0, h1);
            *(uint2*)(sA[0][1] + off) = make_uint2(l0, l1);
        }
    }
    __syncthreads();

    // ldmatrix lane addressing (A: rows lane&15, 16B seg lane>>4).
    const uint32_t aOff = (uint32_t)((wid * 32 + (lane & 15)) * A_STRIDE + (lane >> 4) * 16);
    const int bN0 = (lane & 7) + ((lane >> 4) & 1) * 8;
    const uint32_t bKoff = (uint32_t)(((lane >> 3) & 1) * 16);
    const uint32_t bBaseH0 = smem_u32(sBH) + (uint32_t)(bN0 * B_STRIDE) + bKoff;
    const uint32_t bBaseH1 = bBaseH0 + 16 * B_STRIDE;
    const uint32_t bBaseL0 = smem_u32(sBL) + (uint32_t)(bN0 * B_STRIDE) + bKoff;
    const uint32_t bBaseL1 = bBaseL0 + 16 * B_STRIDE;

    float d[2][4][4];
#pragma unroll
    for (int mt = 0; mt < 2; mt++)
#pragma unroll
        for (int nt = 0; nt < 4; nt++)
#pragma unroll
            for (int r = 0; r < 4; r++) d[mt][nt][r] = 0.0f;

#pragma unroll 1
    for (int c = 0; c < 8; ++c) {
        const int buf = c & 1;
        const uint32_t aBaseH = smem_u32(sA[buf][0]) + aOff;
        const uint32_t aBaseL = smem_u32(sA[buf][1]) + aOff;

        // Prefetch next chunk to registers (overlaps with ldmatrix/MMA).
        float4 pre[8];
        if (c < 7) {
#pragma unroll
            for (int p = 0; p < 8; p++)
                pre[p] = *(const float4*)&emb[(size_t)(rowBase + p * 16 + gRow) * EMB_DIM
                                              + (c + 1) * 32 + gSeg * 4];
        }

        // Two k-sub-steps of 16 within the 32-k chunk.
#pragma unroll
        for (int ks = 0; ks < 2; ++ks) {
            const uint32_t ak = (uint32_t)(ks * 32);        // 16 bf16 = 32 B
            const uint32_t bk = (uint32_t)(c * 64 + ks * 32);
            uint32_t aH[2][4], aL[2][4];
            ldmat_x4(aH[0], aBaseH + ak);
            ldmat_x4(aH[1], aBaseH + ak + 16 * A_STRIDE);
            ldmat_x4(aL[0], aBaseL + ak);
            ldmat_x4(aL[1], aBaseL + ak + 16 * A_STRIDE);
            uint32_t bH01[4], bH23[4], bL01[4], bL23[4];
            ldmat_x4(bH01, bBaseH0 + bk);
            ldmat_x4(bH23, bBaseH1 + bk);
            ldmat_x4(bL01, bBaseL0 + bk);
            ldmat_x4(bL23, bBaseL1 + bk);

#pragma unroll
            for (int mt = 0; mt < 2; mt++) {
                mma_bf16(d[mt][0], aH[mt], bH01[0], bH01[1]);
                mma_bf16(d[mt][1], aH[mt], bH01[2], bH01[3]);
                mma_bf16(d[mt][2], aH[mt], bH23[0], bH23[1]);
                mma_bf16(d[mt][3], aH[mt], bH23[2], bH23[3]);
                mma_bf16(d[mt][0], aL[mt], bH01[0], bH01[1]);
                mma_bf16(d[mt][1], aL[mt], bH01[2], bH01[3]);
                mma_bf16(d[mt][2], aL[mt], bH23[0], bH23[1]);
                mma_bf16(d[mt][3], aL[mt], bH23[2], bH23[3]);
                mma_bf16(d[mt][0], aH[mt], bL01[0], bL01[1]);
                mma_bf16(d[mt][1], aH[mt], bL01[2], bL01[3]);
                mma_bf16(d[mt][2], aH[mt], bL23[0], bL23[1]);
                mma_bf16(d[mt][3], aH[mt], bL23[2], bL23[3]);
            }
        }

        // Store next chunk into the other buffer (its last readers finished
        // before the sync that ended iteration c-1), then one sync.
        if (c < 7) {
            char* dH = sA[buf ^ 1][0];
            char* dL = sA[buf ^ 1][1];
#pragma unroll
            for (int p = 0; p < 8; p++) {
                const int row = p * 16 + gRow;
                uint32_t h0, l0, h1, l1;
                split2(pre[p].x, pre[p].y, h0, l0);
                split2(pre[p].z, pre[p].w, h1, l1);
                const int off = row * A_STRIDE + gSeg * 8;
                *(uint2*)(dH + off) = make_uint2(h0, h1);
                *(uint2*)(dL + off) = make_uint2(l0, l1);
            }
            __syncthreads();
        }
    }

    // ---- Epilogue: D fragments -> g_tbl ----
    const int g = lane >> 2;
    const int cp = (lane & 3) * 2;
#pragma unroll
    for (int mt = 0; mt < 2; mt++) {
        const int r0 = rowBase + wid * 32 + mt * 16 + g;
#pragma unroll
        for (int nt = 0; nt < 4; nt++) {
            const int col = nt * 8 + cp;
            *(float2*)&g_tbl[(size_t)r0 * 32 + col]       = make_float2(d[mt][nt][0], d[mt][nt][1]);
            *(float2*)&g_tbl[(size_t)(r0 + 8) * 32 + col] = make_float2(d[mt][nt][2], d[mt][nt][3]);
        }
    }
}

// ---------------------------------------------------------------------------
// Kernel 2: 16 elems/block, 256 threads, grid 1024.
// Phase 1: thread = (elem, half, seg): sums 16 feature rows' float4 at seg.
//   16 independent LDG.128 per thread -> BW-bound, latency fully pipelined.
// Phase 2: warp per 2 elems: h1 from smem partials, shfl MLP (R7 structure).
// ---------------------------------------------------------------------------
__global__ __launch_bounds__(256)
void k2_forward(const int* __restrict__ indices,
                const float* __restrict__ b1,
                const float* __restrict__ w2,
                const float* __restrict__ b2,
                const float* __restrict__ w3,
                const float* __restrict__ b3,
                float* __restrict__ out) {
    __shared__ __align__(16) float w2s[32 * 36];
    __shared__ float w3s[32];
    __shared__ __align__(16) int   idx_s[16][32];
    __shared__ __align__(16) float part[2][16][32];

    const int tid = threadIdx.x;
    const int b0 = blockIdx.x * 16;

    for (int t = tid; t < 1024; t += 256)
        w2s[(t >> 5) * 36 + (t & 31)] = w2[t];
    if (tid < 32) w3s[tid] = w3[tid];
    for (int t = tid; t < 512; t += 256) {
        const int f = t >> 4, e = t & 15;
        idx_s[e][f] = indices[f * BATCH + b0 + e];     // coalesced 64B runs
    }
    __syncthreads();

    // ---- Phase 1: gather-accumulate ----
    {
        const int e    = tid >> 4;
        const int half = (tid >> 3) & 1;
        const int seg  = tid & 7;
        const int* idxp = &idx_s[e][half * 16];
        float4 acc = make_float4(0.f, 0.f, 0.f, 0.f);
#pragma unroll
        for (int i = 0; i < 16; ++i) {
            const int id = idxp[i];                     // broadcast LDS
            const float4 v = *(const float4*)&g_tbl[(size_t)id * 32 + seg * 4];
            acc.x += v.x; acc.y += v.y; acc.z += v.z; acc.w += v.w;
        }
        *(float4*)&part[half][e][seg * 4] = acc;
    }
    __syncthreads();

    // ---- Phase 2: MLP, warp per 2 elems ----
    const int lane = tid & 31;
    const int e0 = (tid >> 5) * 2;

    float4 wrow[8];
#pragma unroll
    for (int i = 0; i < 8; i++)
        wrow[i] = *(const float4*)&w2s[lane * 36 + i * 4];

    const float bb1 = b1[lane];
    const float h1a = fmaxf(bb1 + part[0][e0][lane]     + part[1][e0][lane],     0.0f);
    const float h1b = fmaxf(bb1 + part[0][e0 + 1][lane] + part[1][e0 + 1][lane], 0.0f);

    float h2a = b2[lane], h2b = h2a;
    const float* wr = (const float*)wrow;
#pragma unroll
    for (int k = 0; k < 32; ++k) {
        const float va = __shfl_sync(FULLMASK, h1a, k);
        const float vb = __shfl_sync(FULLMASK, h1b, k);
        h2a = fmaf(va, wr[k], h2a);
        h2b = fmaf(vb, wr[k], h2b);
    }
    h2a = fmaxf(h2a, 0.0f);
    h2b = fmaxf(h2b, 0.0f);

    float pa = h2a * w3s[lane];
    float pb = h2b * w3s[lane];
#pragma unroll
    for (int off = 16; off; off >>= 1) {
        pa += __shfl_xor_sync(FULLMASK, pa, off);
        pb += __shfl_xor_sync(FULLMASK, pb, off);
    }

    const float r = (lane & 1) ? pb : pa;
    if (lane < 2)
        out[b0 + e0 + lane] = tanhf(r + b3[0]);
}

// ---------------------------------------------------------------------------
extern "C" void kernel_launch(void* const* d_in, const int* in_sizes, int n_in,
                              void* d_out, int out_size) {
    const int*   indices = (const int*)  d_in[0];
    const float* emb     = (const float*)d_in[1];
    const float* w1      = (const float*)d_in[2];
    const float* b1      = (const float*)d_in[3];
    const float* w2      = (const float*)d_in[4];
    const float* b2      = (const float*)d_in[5];
    const float* w3      = (const float*)d_in[6];
    const float* b3      = (const float*)d_in[7];
    float* out = (float*)d_out;

    static bool attr_set = false;
    if (!attr_set) {
        cudaFuncSetAttribute(k1_precompute,
                             cudaFuncAttributeMaxDynamicSharedMemorySize, K1_SMEM);
        attr_set = true;
    }

    k1_precompute<<<INPUT_DIM / 128, 128, K1_SMEM>>>(emb, w1);         // 384 blocks
    k2_forward<<<BATCH / 16, 256>>>(indices, b1, w2, b2, w3, b3, out); // 1024 blocks
}

// round 11
// speedup vs baseline: 2.1511x; 1.1535x over previous
#include <cuda_runtime.h>
#include <cuda_fp16.h>
#include <cstdint>

// ---------------------------------------------------------------------------
// NNUE: out[b] = tanh(relu(relu((sum_f emb[idx[f,b]]) @ w1^T + b1) @ w2^T + b2) @ w3^T + b3)
//
// K1: g_tbl = emb @ w1^T ([49152,32]) via mma.sync.m16n8k16 FP16, 2 terms:
//     A = rn_fp16(emb) (single), B = Bh + Bl (fp16 hi/lo split of w1).
//     D = Ah*Bh + Ah*Bl, f32 accum. Error ~2^-12 from A rounding -> ~1e-4,
//     inside the 1e-3 budget with >=10x margin.
// K2: 32-feature gather (128B rows) + tiny MLP. 32 elems/block, grid 512
//     (single resident wave), 2 gather chains per thread, 4 elems per warp
//     in the MLP phase.
// ---------------------------------------------------------------------------

#define FULLMASK 0xffffffffu

constexpr int INPUT_DIM = 49152;
constexpr int EMB_DIM   = 256;
constexpr int BATCH     = 16384;

__device__ float g_tbl[INPUT_DIM * 32];

__device__ __forceinline__ uint32_t smem_u32(const void* p) {
    uint32_t a;
    asm("{ .reg .u64 t; cvta.to.shared.u64 t, %1; cvt.u32.u64 %0, t; }" : "=r"(a) : "l"(p));
    return a;
}
__device__ __forceinline__ void ldmat_x4(uint32_t r[4], uint32_t addr) {
    asm volatile("ldmatrix.sync.aligned.m8n8.x4.shared.b16 {%0,%1,%2,%3}, [%4];"
                 : "=r"(r[0]), "=r"(r[1]), "=r"(r[2]), "=r"(r[3]) : "r"(addr));
}
__device__ __forceinline__ void mma_f16(float d[4], const uint32_t a[4],
                                        uint32_t b0, uint32_t b1) {
    asm volatile("mma.sync.aligned.m16n8k16.row.col.f32.f16.f16.f32 "
                 "{%0,%1,%2,%3}, {%4,%5,%6,%7}, {%8,%9}, {%0,%1,%2,%3};"
                 : "+f"(d[0]), "+f"(d[1]), "+f"(d[2]), "+f"(d[3])
                 : "r"(a[0]), "r"(a[1]), "r"(a[2]), "r"(a[3]), "r"(b0), "r"(b1));
}
__device__ __forceinline__ uint32_t cvt2h(float x, float y) {
    __half2 h = __float22half2_rn(make_float2(x, y));
    return *(uint32_t*)&h;
}
__device__ __forceinline__ void split2h(float x, float y, uint32_t& hi, uint32_t& lo) {
    __half2 h = __float22half2_rn(make_float2(x, y));
    float2 hf = __half22float2(h);
    __half2 l = __float22half2_rn(make_float2(x - hf.x, y - hf.y));
    hi = *(uint32_t*)&h;
    lo = *(uint32_t*)&l;
}

// ---------------------------------------------------------------------------
// Kernel 1.  CTA: 128 threads = 4 warps; 128 rows; grid 384.
// K in 8 chunks of 32; A (fp16, single) double-buffered; BH/BL resident.
// Dynamic smem: 2 A-stages x 10240 + BH/BL x 16896 = 54272 B.
// Per chunk per warp: 12 ldmatrix.x4 + 32 HMMA + ~50 conv/LDG/STS + 1 sync.
// ---------------------------------------------------------------------------
constexpr int A_STRIDE = 80;    // bytes per A row: 32 fp16 = 64 + 16 pad
constexpr int B_STRIDE = 528;   // bytes per B row: 256 fp16 = 512 + 16 pad
constexpr int SZ_A = 128 * A_STRIDE;                  // 10240
constexpr int SZ_B = 32 * B_STRIDE;                   // 16896
constexpr int K1_SMEM = 2 * SZ_A + 2 * SZ_B;          // 54272

__global__ __launch_bounds__(128)
void k1_precompute(const float* __restrict__ emb, const float* __restrict__ w1) {
    extern __shared__ __align__(16) char dsm[];
    char* sA0 = dsm;
    char* sA1 = dsm + SZ_A;
    char* sBH = dsm + 2 * SZ_A;
    char* sBL = sBH + SZ_B;

    const int tid  = threadIdx.x;
    const int wid  = tid >> 5;
    const int lane = tid & 31;
    const int rowBase = blockIdx.x * 128;

    // ---- Prologue: split w1 (32x256) into BH/BL fp16 ----
    {
        const float4* src = (const float4*)w1;
        for (int i = tid; i < 2048; i += 128) {
            const float4 v = src[i];
            const int n = i >> 6;
            const int k = (i & 63) * 4;
            uint32_t h0, l0, h1, l1;
            split2h(v.x, v.y, h0, l0);
            split2h(v.z, v.w, h1, l1);
            const int off = n * B_STRIDE + k * 2;
            *(uint2*)(sBH + off) = make_uint2(h0, h1);
            *(uint2*)(sBL + off) = make_uint2(l0, l1);
        }
    }

    const int gRow = tid >> 3;          // 0..15
    const int gSeg = tid & 7;           // 0..7 (float4 seg of 32-k window)

    // ---- Stage chunk 0 into buffer 0 ----
#pragma unroll
    for (int p = 0; p < 8; p++) {
        const int row = p * 16 + gRow;
        const float4 v = *(const float4*)&emb[(size_t)(rowBase + row) * EMB_DIM + gSeg * 4];
        *(uint2*)(sA0 + row * A_STRIDE + gSeg * 8) =
            make_uint2(cvt2h(v.x, v.y), cvt2h(v.z, v.w));
    }
    __syncthreads();

    const uint32_t aOff = (uint32_t)((wid * 32 + (lane & 15)) * A_STRIDE + (lane >> 4) * 16);
    const int bN0 = (lane & 7) + ((lane >> 4) & 1) * 8;
    const uint32_t bKoff = (uint32_t)(((lane >> 3) & 1) * 16);
    const uint32_t bBaseH0 = smem_u32(sBH) + (uint32_t)(bN0 * B_STRIDE) + bKoff;
    const uint32_t bBaseH1 = bBaseH0 + 16 * B_STRIDE;
    const uint32_t bBaseL0 = smem_u32(sBL) + (uint32_t)(bN0 * B_STRIDE) + bKoff;
    const uint32_t bBaseL1 = bBaseL0 + 16 * B_STRIDE;
    const uint32_t aB0 = smem_u32(sA0) + aOff;
    const uint32_t aB1 = smem_u32(sA1) + aOff;

    float d[2][4][4];
#pragma unroll
    for (int mt = 0; mt < 2; mt++)
#pragma unroll
        for (int nt = 0; nt < 4; nt++)
#pragma unroll
            for (int r = 0; r < 4; r++) d[mt][nt][r] = 0.0f;

#pragma unroll 1
    for (int c = 0; c < 8; ++c) {
        const uint32_t aBase = (c & 1) ? aB1 : aB0;

        float4 pre[8];
        if (c < 7) {
#pragma unroll
            for (int p = 0; p < 8; p++)
                pre[p] = *(const float4*)&emb[(size_t)(rowBase + p * 16 + gRow) * EMB_DIM
                                              + (c + 1) * 32 + gSeg * 4];
        }

#pragma unroll
        for (int ks = 0; ks < 2; ++ks) {
            const uint32_t ak = (uint32_t)(ks * 32);        // 16 fp16 = 32 B
            const uint32_t bk = (uint32_t)(c * 64 + ks * 32);
            uint32_t aH[2][4];
            ldmat_x4(aH[0], aBase + ak);
            ldmat_x4(aH[1], aBase + ak + 16 * A_STRIDE);
            uint32_t bH01[4], bH23[4], bL01[4], bL23[4];
            ldmat_x4(bH01, bBaseH0 + bk);
            ldmat_x4(bH23, bBaseH1 + bk);
            ldmat_x4(bL01, bBaseL0 + bk);
            ldmat_x4(bL23, bBaseL1 + bk);

#pragma unroll
            for (int mt = 0; mt < 2; mt++) {
                mma_f16(d[mt][0], aH[mt], bH01[0], bH01[1]);
                mma_f16(d[mt][1], aH[mt], bH01[2], bH01[3]);
                mma_f16(d[mt][2], aH[mt], bH23[0], bH23[1]);
                mma_f16(d[mt][3], aH[mt], bH23[2], bH23[3]);
                mma_f16(d[mt][0], aH[mt], bL01[0], bL01[1]);
                mma_f16(d[mt][1], aH[mt], bL01[2], bL01[3]);
                mma_f16(d[mt][2], aH[mt], bL23[0], bL23[1]);
                mma_f16(d[mt][3], aH[mt], bL23[2], bL23[3]);
            }
        }

        if (c < 7) {
            char* dst = (c & 1) ? sA0 : sA1;
#pragma unroll
            for (int p = 0; p < 8; p++) {
                const int row = p * 16 + gRow;
                *(uint2*)(dst + row * A_STRIDE + gSeg * 8) =
                    make_uint2(cvt2h(pre[p].x, pre[p].y), cvt2h(pre[p].z, pre[p].w));
            }
            __syncthreads();
        }
    }

    // ---- Epilogue: D fragments -> g_tbl ----
    const int g = lane >> 2;
    const int cp = (lane & 3) * 2;
#pragma unroll
    for (int mt = 0; mt < 2; mt++) {
        const int r0 = rowBase + wid * 32 + mt * 16 + g;
#pragma unroll
        for (int nt = 0; nt < 4; nt++) {
            const int col = nt * 8 + cp;
            *(float2*)&g_tbl[(size_t)r0 * 32 + col]       = make_float2(d[mt][nt][0], d[mt][nt][1]);
            *(float2*)&g_tbl[(size_t)(r0 + 8) * 32 + col] = make_float2(d[mt][nt][2], d[mt][nt][3]);
        }
    }
}

// ---------------------------------------------------------------------------
// Kernel 2: 32 elems/block, 256 threads, grid 512 (~single resident wave).
// Phase 1: thread runs 2 chains (elem e and e+16, same half/seg): 2x16
//   independent LDG.128 in flight.
// Phase 2: warp per 4 elems: h1 from smem partials, 4 interleaved shfl MLPs.
// ---------------------------------------------------------------------------
__global__ __launch_bounds__(256)
void k2_forward(const int* __restrict__ indices,
                const float* __restrict__ b1,
                const float* __restrict__ w2,
                const float* __restrict__ b2,
                const float* __restrict__ w3,
                const float* __restrict__ b3,
                float* __restrict__ out) {
    __shared__ __align__(16) float w2s[32 * 36];
    __shared__ float w3s[32];
    __shared__ int   idx_s[32][33];
    __shared__ __align__(16) float part[2][32][32];

    const int tid = threadIdx.x;
    const int b0 = blockIdx.x * 32;

    for (int t = tid; t < 1024; t += 256)
        w2s[(t >> 5) * 36 + (t & 31)] = w2[t];
    if (tid < 32) w3s[tid] = w3[tid];
    for (int t = tid; t < 1024; t += 256) {
        const int f = t >> 5, e = t & 31;
        idx_s[e][f] = indices[f * BATCH + b0 + e];     // coalesced 128B runs
    }
    __syncthreads();

    // ---- Phase 1: gather-accumulate, 2 chains per thread ----
    {
        const int e    = tid >> 4;          // 0..15 (chain B uses e+16)
        const int half = (tid >> 3) & 1;
        const int seg  = tid & 7;
        const int* ia = &idx_s[e][half * 16];
        const int* ib = &idx_s[e + 16][half * 16];
        float4 accA = make_float4(0.f, 0.f, 0.f, 0.f);
        float4 accB = make_float4(0.f, 0.f, 0.f, 0.f);
#pragma unroll
        for (int i = 0; i < 16; ++i) {
            const float4 va = *(const float4*)&g_tbl[(size_t)ia[i] * 32 + seg * 4];
            const float4 vb = *(const float4*)&g_tbl[(size_t)ib[i] * 32 + seg * 4];
            accA.x += va.x; accA.y += va.y; accA.z += va.z; accA.w += va.w;
            accB.x += vb.x; accB.y += vb.y; accB.z += vb.z; accB.w += vb.w;
        }
        *(float4*)&part[half][e][seg * 4]      = accA;
        *(float4*)&part[half][e + 16][seg * 4] = accB;
    }
    __syncthreads();

    // ---- Phase 2: MLP, warp per 4 elems ----
    const int lane = tid & 31;
    const int e0 = (tid >> 5) * 4;

    float4 wrow[8];
#pragma unroll
    for (int i = 0; i < 8; i++)
        wrow[i] = *(const float4*)&w2s[lane * 36 + i * 4];
    const float* wr = (const float*)wrow;

    const float bb1 = b1[lane];
    const float bb2 = b2[lane];
    const float w3l = w3s[lane];

    float h1[4], h2[4];
#pragma unroll
    for (int j = 0; j < 4; j++) {
        h1[j] = fmaxf(bb1 + part[0][e0 + j][lane] + part[1][e0 + j][lane], 0.0f);
        h2[j] = bb2;
    }
#pragma unroll
    for (int k = 0; k < 32; ++k) {
#pragma unroll
        for (int j = 0; j < 4; j++) {
            const float v = __shfl_sync(FULLMASK, h1[j], k);
            h2[j] = fmaf(v, wr[k], h2[j]);
        }
    }
    float p[4];
#pragma unroll
    for (int j = 0; j < 4; j++)
        p[j] = fmaxf(h2[j], 0.0f) * w3l;
#pragma unroll
    for (int off = 16; off; off >>= 1)
#pragma unroll
        for (int j = 0; j < 4; j++)
            p[j] += __shfl_xor_sync(FULLMASK, p[j], off);

    float r = p[0];
    if (lane == 1) r = p[1];
    if (lane == 2) r = p[2];
    if (lane == 3) r = p[3];
    if (lane < 4)
        out[b0 + e0 + lane] = tanhf(r + b3[0]);
}

// ---------------------------------------------------------------------------
extern "C" void kernel_launch(void* const* d_in, const int* in_sizes, int n_in,
                              void* d_out, int out_size) {
    const int*   indices = (const int*)  d_in[0];
    const float* emb     = (const float*)d_in[1];
    const float* w1      = (const float*)d_in[2];
    const float* b1      = (const float*)d_in[3];
    const float* w2      = (const float*)d_in[4];
    const float* b2      = (const float*)d_in[5];
    const float* w3      = (const float*)d_in[6];
    const float* b3      = (const float*)d_in[7];
    float* out = (float*)d_out;

    static bool attr_set = false;
    if (!attr_set) {
        cudaFuncSetAttribute(k1_precompute,
                             cudaFuncAttributeMaxDynamicSharedMemorySize, K1_SMEM);
        attr_set = true;
    }

    k1_precompute<<<INPUT_DIM / 128, 128, K1_SMEM>>>(emb, w1);         // 384 blocks
    k2_forward<<<BATCH / 32, 256>>>(indices, b1, w2, b2, w3, b3, out); // 512 blocks
}

// round 12
// speedup vs baseline: 2.3359x; 1.0859x over previous
#include <cuda_runtime.h>
#include <cuda_fp16.h>
#include <cstdint>

// ---------------------------------------------------------------------------
// NNUE: out[b] = tanh(relu(relu((sum_f emb[idx[f,b]]) @ w1^T + b1) @ w2^T + b2) @ w3^T + b3)
//
// K1: g_tbl = emb @ w1^T ([49152,32]) via mma.sync.m16n8k16 FP16 single-term
//     (A = rn_fp16(emb), B = rn_fp16(w1), f32 accum). g_tbl stored as fp16.
// K2: 32-feature gather (64B fp16 rows) + tiny MLP. 16 elems/block, grid
//     1024 (the measured-best occupancy shape), fp32 accumulation.
// Error budget: 3 independent ~1e-4 rounding sources -> ~2e-4 rss, vs 1e-3.
// ---------------------------------------------------------------------------

#define FULLMASK 0xffffffffu

constexpr int INPUT_DIM = 49152;
constexpr int EMB_DIM   = 256;
constexpr int BATCH     = 16384;

__device__ __half g_tbl[INPUT_DIM * 32];

__device__ __forceinline__ uint32_t smem_u32(const void* p) {
    uint32_t a;
    asm("{ .reg .u64 t; cvta.to.shared.u64 t, %1; cvt.u32.u64 %0, t; }" : "=r"(a) : "l"(p));
    return a;
}
__device__ __forceinline__ void ldmat_x4(uint32_t r[4], uint32_t addr) {
    asm volatile("ldmatrix.sync.aligned.m8n8.x4.shared.b16 {%0,%1,%2,%3}, [%4];"
                 : "=r"(r[0]), "=r"(r[1]), "=r"(r[2]), "=r"(r[3]) : "r"(addr));
}
__device__ __forceinline__ void mma_f16(float d[4], const uint32_t a[4],
                                        uint32_t b0, uint32_t b1) {
    asm volatile("mma.sync.aligned.m16n8k16.row.col.f32.f16.f16.f32 "
                 "{%0,%1,%2,%3}, {%4,%5,%6,%7}, {%8,%9}, {%0,%1,%2,%3};"
                 : "+f"(d[0]), "+f"(d[1]), "+f"(d[2]), "+f"(d[3])
                 : "r"(a[0]), "r"(a[1]), "r"(a[2]), "r"(a[3]), "r"(b0), "r"(b1));
}
__device__ __forceinline__ uint32_t cvt2h(float x, float y) {
    __half2 h = __float22half2_rn(make_float2(x, y));
    return *(uint32_t*)&h;
}

// ---------------------------------------------------------------------------
// Kernel 1.  CTA: 128 threads = 4 warps; 128 rows; grid 384.
// K in 8 chunks of 32; A (fp16) double-buffered; B (fp16) resident.
// Dynamic smem: 2 x 10240 + 16896 = 37376 B.
// Per chunk per warp: 8 ldmatrix.x4 + 16 HMMA + conv/LDG/STS + 1 sync.
// ---------------------------------------------------------------------------
constexpr int A_STRIDE = 80;    // bytes per A row: 32 fp16 = 64 + 16 pad
constexpr int B_STRIDE = 528;   // bytes per B row: 256 fp16 = 512 + 16 pad
constexpr int SZ_A = 128 * A_STRIDE;                  // 10240
constexpr int SZ_B = 32 * B_STRIDE;                   // 16896
constexpr int K1_SMEM = 2 * SZ_A + SZ_B;              // 37376

__global__ __launch_bounds__(128)
void k1_precompute(const float* __restrict__ emb, const float* __restrict__ w1) {
    extern __shared__ __align__(16) char dsm[];
    char* sA0 = dsm;
    char* sA1 = dsm + SZ_A;
    char* sB  = dsm + 2 * SZ_A;

    const int tid  = threadIdx.x;
    const int wid  = tid >> 5;
    const int lane = tid & 31;
    const int rowBase = blockIdx.x * 128;

    // ---- Prologue: convert w1 (32x256) to fp16 ----
    {
        const float4* src = (const float4*)w1;
        for (int i = tid; i < 2048; i += 128) {
            const float4 v = src[i];
            const int n = i >> 6;
            const int k = (i & 63) * 4;
            *(uint2*)(sB + n * B_STRIDE + k * 2) =
                make_uint2(cvt2h(v.x, v.y), cvt2h(v.z, v.w));
        }
    }

    const int gRow = tid >> 3;          // 0..15
    const int gSeg = tid & 7;           // 0..7 (float4 seg of 32-k window)

    // ---- Stage chunk 0 into buffer 0 ----
#pragma unroll
    for (int p = 0; p < 8; p++) {
        const int row = p * 16 + gRow;
        const float4 v = *(const float4*)&emb[(size_t)(rowBase + row) * EMB_DIM + gSeg * 4];
        *(uint2*)(sA0 + row * A_STRIDE + gSeg * 8) =
            make_uint2(cvt2h(v.x, v.y), cvt2h(v.z, v.w));
    }
    __syncthreads();

    const uint32_t aOff = (uint32_t)((wid * 32 + (lane & 15)) * A_STRIDE + (lane >> 4) * 16);
    const int bN0 = (lane & 7) + ((lane >> 4) & 1) * 8;
    const uint32_t bKoff = (uint32_t)(((lane >> 3) & 1) * 16);
    const uint32_t bBase0 = smem_u32(sB) + (uint32_t)(bN0 * B_STRIDE) + bKoff;
    const uint32_t bBase1 = bBase0 + 16 * B_STRIDE;
    const uint32_t aB0 = smem_u32(sA0) + aOff;
    const uint32_t aB1 = smem_u32(sA1) + aOff;

    float d[2][4][4];
#pragma unroll
    for (int mt = 0; mt < 2; mt++)
#pragma unroll
        for (int nt = 0; nt < 4; nt++)
#pragma unroll
            for (int r = 0; r < 4; r++) d[mt][nt][r] = 0.0f;

#pragma unroll 1
    for (int c = 0; c < 8; ++c) {
        const uint32_t aBase = (c & 1) ? aB1 : aB0;

        float4 pre[8];
        if (c < 7) {
#pragma unroll
            for (int p = 0; p < 8; p++)
                pre[p] = *(const float4*)&emb[(size_t)(rowBase + p * 16 + gRow) * EMB_DIM
                                              + (c + 1) * 32 + gSeg * 4];
        }

#pragma unroll
        for (int ks = 0; ks < 2; ++ks) {
            const uint32_t ak = (uint32_t)(ks * 32);        // 16 fp16 = 32 B
            const uint32_t bk = (uint32_t)(c * 64 + ks * 32);
            uint32_t aH[2][4];
            ldmat_x4(aH[0], aBase + ak);
            ldmat_x4(aH[1], aBase + ak + 16 * A_STRIDE);
            uint32_t b01[4], b23[4];
            ldmat_x4(b01, bBase0 + bk);
            ldmat_x4(b23, bBase1 + bk);

#pragma unroll
            for (int mt = 0; mt < 2; mt++) {
                mma_f16(d[mt][0], aH[mt], b01[0], b01[1]);
                mma_f16(d[mt][1], aH[mt], b01[2], b01[3]);
                mma_f16(d[mt][2], aH[mt], b23[0], b23[1]);
                mma_f16(d[mt][3], aH[mt], b23[2], b23[3]);
            }
        }

        if (c < 7) {
            char* dst = (c & 1) ? sA0 : sA1;
#pragma unroll
            for (int p = 0; p < 8; p++) {
                const int row = p * 16 + gRow;
                *(uint2*)(dst + row * A_STRIDE + gSeg * 8) =
                    make_uint2(cvt2h(pre[p].x, pre[p].y), cvt2h(pre[p].z, pre[p].w));
            }
            __syncthreads();
        }
    }

    // ---- Epilogue: D fragments -> fp16 g_tbl ----
    const int g = lane >> 2;
    const int cp = (lane & 3) * 2;
#pragma unroll
    for (int mt = 0; mt < 2; mt++) {
        const int r0 = rowBase + wid * 32 + mt * 16 + g;
#pragma unroll
        for (int nt = 0; nt < 4; nt++) {
            const int col = nt * 8 + cp;
            *(__half2*)&g_tbl[(size_t)r0 * 32 + col] =
                __float22half2_rn(make_float2(d[mt][nt][0], d[mt][nt][1]));
            *(__half2*)&g_tbl[(size_t)(r0 + 8) * 32 + col] =
                __float22half2_rn(make_float2(d[mt][nt][2], d[mt][nt][3]));
        }
    }
}

// ---------------------------------------------------------------------------
// Kernel 2: 16 elems/block, 256 threads, grid 1024 (R10's best occupancy).
// Phase 1: thread = (elem, feature-quarter q, 16B-seg s): sums 8 fp16 rows'
//   16B segment in fp32 (8 independent LDG.128 per thread; rows are 64B).
// Phase 2: warp per 2 elems: h1 = b1 + sum_q part, shfl MLP (R10 structure).
// ---------------------------------------------------------------------------
__global__ __launch_bounds__(256)
void k2_forward(const int* __restrict__ indices,
                const float* __restrict__ b1,
                const float* __restrict__ w2,
                const float* __restrict__ b2,
                const float* __restrict__ w3,
                const float* __restrict__ b3,
                float* __restrict__ out) {
    __shared__ __align__(16) float w2s[32 * 36];
    __shared__ float w3s[32];
    __shared__ int   idx_s[16][33];
    __shared__ __align__(16) float part[4][16][32];

    const int tid = threadIdx.x;
    const int b0 = blockIdx.x * 16;

    for (int t = tid; t < 1024; t += 256)
        w2s[(t >> 5) * 36 + (t & 31)] = w2[t];
    if (tid < 32) w3s[tid] = w3[tid];
    for (int t = tid; t < 512; t += 256) {
        const int f = t >> 4, e = t & 15;
        idx_s[e][f] = indices[f * BATCH + b0 + e];     // coalesced 64B runs
    }
    __syncthreads();

    // ---- Phase 1: gather-accumulate (fp16 rows, fp32 accum) ----
    {
        const int e = tid >> 4;             // 0..15
        const int q = (tid >> 2) & 3;       // feature quarter (8 feats)
        const int s = tid & 3;              // 16B segment (8 cols)
        const int* idxp = &idx_s[e][q * 8];
        float acc[8];
#pragma unroll
        for (int j = 0; j < 8; j++) acc[j] = 0.0f;
#pragma unroll
        for (int i = 0; i < 8; ++i) {
            const int id = idxp[i];                     // broadcast LDS
            const uint4 v = *(const uint4*)((const char*)g_tbl + ((size_t)id << 6) + s * 16);
            const __half2* hp = (const __half2*)&v;
#pragma unroll
            for (int j = 0; j < 4; j++) {
                const float2 f2 = __half22float2(hp[j]);
                acc[2 * j]     += f2.x;
                acc[2 * j + 1] += f2.y;
            }
        }
        float* dst = &part[q][e][s * 8];
        *(float4*)(dst)     = make_float4(acc[0], acc[1], acc[2], acc[3]);
        *(float4*)(dst + 4) = make_float4(acc[4], acc[5], acc[6], acc[7]);
    }
    __syncthreads();

    // ---- Phase 2: MLP, warp per 2 elems ----
    const int lane = tid & 31;
    const int e0 = (tid >> 5) * 2;

    float4 wrow[8];
#pragma unroll
    for (int i = 0; i < 8; i++)
        wrow[i] = *(const float4*)&w2s[lane * 36 + i * 4];
    const float* wr = (const float*)wrow;

    const float bb1 = b1[lane];
    const float h1a = fmaxf(bb1 + (part[0][e0][lane] + part[1][e0][lane])
                                + (part[2][e0][lane] + part[3][e0][lane]), 0.0f);
    const float h1b = fmaxf(bb1 + (part[0][e0 + 1][lane] + part[1][e0 + 1][lane])
                                + (part[2][e0 + 1][lane] + part[3][e0 + 1][lane]), 0.0f);

    float h2a = b2[lane], h2b = h2a;
#pragma unroll
    for (int k = 0; k < 32; ++k) {
        const float va = __shfl_sync(FULLMASK, h1a, k);
        const float vb = __shfl_sync(FULLMASK, h1b, k);
        h2a = fmaf(va, wr[k], h2a);
        h2b = fmaf(vb, wr[k], h2b);
    }
    h2a = fmaxf(h2a, 0.0f);
    h2b = fmaxf(h2b, 0.0f);

    float pa = h2a * w3s[lane];
    float pb = h2b * w3s[lane];
#pragma unroll
    for (int off = 16; off; off >>= 1) {
        pa += __shfl_xor_sync(FULLMASK, pa, off);
        pb += __shfl_xor_sync(FULLMASK, pb, off);
    }

    const float r = (lane & 1) ? pb : pa;
    if (lane < 2)
        out[b0 + e0 + lane] = tanhf(r + b3[0]);
}

// ---------------------------------------------------------------------------
extern "C" void kernel_launch(void* const* d_in, const int* in_sizes, int n_in,
                              void* d_out, int out_size) {
    const int*   indices = (const int*)  d_in[0];
    const float* emb     = (const float*)d_in[1];
    const float* w1      = (const float*)d_in[2];
    const float* b1      = (const float*)d_in[3];
    const float* w2      = (const float*)d_in[4];
    const float* b2      = (const float*)d_in[5];
    const float* w3      = (const float*)d_in[6];
    const float* b3      = (const float*)d_in[7];
    float* out = (float*)d_out;

    static bool attr_set = false;
    if (!attr_set) {
        cudaFuncSetAttribute(k1_precompute,
                             cudaFuncAttributeMaxDynamicSharedMemorySize, K1_SMEM);
        attr_set = true;
    }

    k1_precompute<<<INPUT_DIM / 128, 128, K1_SMEM>>>(emb, w1);         // 384 blocks
    k2_forward<<<BATCH / 16, 256>>>(indices, b1, w2, b2, w3, b3, out); // 1024 blocks
}